// round 1
// baseline (speedup 1.0000x reference)
#include <cuda_runtime.h>

#define N_VOX 200000
#define ND_VOX 25000
#define NFW 128

// ---------------- scratch (static device globals; no allocation) ----------------
__device__ float g_a[(size_t)N_VOX * 128];   // bnsilu(x) [N,64], later bnsilu(h) [N,128]
__device__ float g_h[(size_t)N_VOX * 128];   // conv1 output h [N,128]
__device__ float g_h2[(size_t)N_VOX * 128];  // idconv base + conv2 output [N,128]
__device__ float g_stats[384];               // sum1[64], sq1[64], sum2[128], sq2[128]
__device__ float g_bn[384];                  // s1[64], b1[64], s2[128], b2[128]
__device__ float g_tp[16 * 256];             // time proj [B, 2*NF]

__device__ __forceinline__ float silu_(float z) {
    return z * (1.f / (1.f + __expf(-z)));
}

// ---------------- packed fp32x2 helpers (exact fp32 math, 2x FMA rate) ----------
__device__ __forceinline__ void ffma2(unsigned long long& d, unsigned long long a, unsigned long long b) {
    asm("fma.rn.f32x2 %0, %1, %2, %0;" : "+l"(d) : "l"(a), "l"(b));
}
__device__ __forceinline__ unsigned long long packf2(float a) {
    unsigned long long r;
    asm("mov.b64 %0, {%1, %1};" : "=l"(r) : "f"(a));
    return r;
}
__device__ __forceinline__ float2 unpackf2(unsigned long long v) {
    float2 r;
    asm("mov.b64 {%0, %1}, %2;" : "=f"(r.x), "=f"(r.y) : "l"(v));
    return r;
}

// ---------------- small kernels ----------------
__global__ void zero_stats_kernel(float* stats) {
    if (threadIdx.x < 384) stats[threadIdx.x] = 0.f;
}

template <int C>
__global__ void stats_kernel(const float* __restrict__ X, int M,
                             float* __restrict__ gsum, float* __restrict__ gsq) {
    constexpr int RPB = 256 / C;
    const int c = threadIdx.x & (C - 1);
    const int rg = threadIdx.x / C;
    float s = 0.f, q = 0.f;
    for (int r = blockIdx.x * RPB + rg; r < M; r += gridDim.x * RPB) {
        float v = X[(size_t)r * C + c];
        s += v;
        q += v * v;
    }
    __shared__ float sh[256];
    __shared__ float sh2[256];
    sh[threadIdx.x] = s;
    sh2[threadIdx.x] = q;
    __syncthreads();
    if (threadIdx.x < C) {
        #pragma unroll
        for (int g = 1; g < RPB; ++g) {
            s += sh[g * C + c];
            q += sh2[g * C + c];
        }
        atomicAdd(&gsum[c], s);
        atomicAdd(&gsq[c], q);
    }
}

__global__ void finalize_bn_kernel(const float* __restrict__ gsum, const float* __restrict__ gsq,
                                   const float* __restrict__ g, const float* __restrict__ be,
                                   float invM, int C,
                                   float* __restrict__ oscale, float* __restrict__ obias) {
    int c = threadIdx.x;
    if (c < C) {
        float m = gsum[c] * invM;
        float v = gsq[c] * invM - m * m;
        float a = g[c] * rsqrtf(v + 1e-5f);
        oscale[c] = a;
        obias[c] = be[c] - m * a;
    }
}

__global__ void bnsilu_kernel(const float* __restrict__ X, const float* __restrict__ sc,
                              const float* __restrict__ bi, size_t total, int cmask,
                              float* __restrict__ out) {
    for (size_t i = (size_t)blockIdx.x * blockDim.x + threadIdx.x; i < total;
         i += (size_t)gridDim.x * blockDim.x) {
        int c = (int)(i & (size_t)cmask);
        float z = X[i] * sc[c] + bi[c];
        out[i] = silu_(z);
    }
}

__global__ void temb_kernel(const float* __restrict__ t, const float* __restrict__ Wt,
                            const float* __restrict__ bt, float* __restrict__ tp) {
    __shared__ float st[256];
    const int b = blockIdx.x, j = threadIdx.x;
    float v = t[b * 256 + j];
    st[j] = silu_(v);
    __syncthreads();
    float acc = bt[j];
    #pragma unroll 8
    for (int e = 0; e < 256; ++e) acc += st[e] * Wt[e * 256 + j];
    tp[b * 256 + j] = acc;
}

// ---------------- gathered sparse-conv GEMM ----------------
// out[i, f] = sum_k A[nbr[k,i], :] @ W[k, :, f]   (nbr < 0 -> zero contribution)
// MODE 0: + bias + bias2 (optional)
// MODE 1: + bias, then time-embedding affine: (1+tp[b,f])*h + tp[b,128+f]
// MODE 2: accumulate on top of existing out contents
// IDENT:  gather index == row (identity conv), nbr ignored
template <int CIN, int MODE, bool IDENT>
__global__ void conv_kernel(const float* __restrict__ A, const int* __restrict__ nbr,
                            int K, int M,
                            const float* __restrict__ W,
                            const float* __restrict__ bias, const float* __restrict__ bias2,
                            float* __restrict__ out,
                            const float* __restrict__ tp, const int* __restrict__ b_idx) {
    extern __shared__ float smem[];
    float* Asm = smem;               // [64][CIN]
    float* Wsm = smem + 64 * CIN;    // [32][128]

    const int tid = threadIdx.x;
    const int tx = tid & 31;   // col group: cols 4*tx .. 4*tx+3
    const int ty = tid >> 5;   // row group: rows ty, ty+8, ..., ty+56
    const int tile = blockIdx.x * 64;

    unsigned long long acc2[8][2];
    if (MODE == 2) {
        #pragma unroll
        for (int r = 0; r < 8; ++r) {
            int row = tile + ty + 8 * r;
            if (row < M) {
                ulonglong2 v = *(const ulonglong2*)(out + (size_t)row * NFW + tx * 4);
                acc2[r][0] = v.x;
                acc2[r][1] = v.y;
            } else {
                acc2[r][0] = 0ull;
                acc2[r][1] = 0ull;
            }
        }
    } else {
        #pragma unroll
        for (int r = 0; r < 8; ++r) { acc2[r][0] = 0ull; acc2[r][1] = 0ull; }
    }

    constexpr int C4 = CIN / 4;

    for (int k = 0; k < K; ++k) {
        // gather A tile [64, CIN] into smem (zeros for missing neighbors)
        for (int i = tid; i < 64 * C4; i += 256) {
            int r = i / C4;
            int c4 = i - r * C4;
            int row = tile + r;
            int idx = -1;
            if (row < M) idx = IDENT ? row : nbr[(size_t)k * M + row];
            float4 v = make_float4(0.f, 0.f, 0.f, 0.f);
            if (idx >= 0) v = *(const float4*)(A + (size_t)idx * CIN + c4 * 4);
            *(float4*)(Asm + r * CIN + c4 * 4) = v;
        }
        __syncthreads();

        for (int cc = 0; cc < CIN; cc += 32) {
            const float* Wk = W + ((size_t)k * CIN + cc) * NFW;
            #pragma unroll
            for (int u = 0; u < 4; ++u) {
                int i = tid + u * 256;
                int wr = i >> 5, wc4 = i & 31;
                *(float4*)(Wsm + wr * NFW + wc4 * 4) = *(const float4*)(Wk + wr * NFW + wc4 * 4);
            }
            __syncthreads();

            #pragma unroll
            for (int c = 0; c < 32; ++c) {
                ulonglong2 w = *(const ulonglong2*)(Wsm + c * NFW + tx * 4);
                #pragma unroll
                for (int r = 0; r < 8; ++r) {
                    unsigned long long aa = packf2(Asm[(ty + 8 * r) * CIN + cc + c]);
                    ffma2(acc2[r][0], aa, w.x);
                    ffma2(acc2[r][1], aa, w.y);
                }
            }
            __syncthreads();
        }
    }

    // epilogue
    #pragma unroll
    for (int r = 0; r < 8; ++r) {
        int row = tile + ty + 8 * r;
        if (row >= M) continue;
        float2 v0 = unpackf2(acc2[r][0]);
        float2 v1 = unpackf2(acc2[r][1]);
        float o0 = v0.x, o1 = v0.y, o2 = v1.x, o3 = v1.y;
        const int col = tx * 4;

        if (MODE == 0) {
            if (bias) {
                o0 += bias[col + 0]; o1 += bias[col + 1];
                o2 += bias[col + 2]; o3 += bias[col + 3];
            }
            if (bias2) {
                o0 += bias2[col + 0]; o1 += bias2[col + 1];
                o2 += bias2[col + 2]; o3 += bias2[col + 3];
            }
        } else if (MODE == 1) {
            o0 += bias[col + 0]; o1 += bias[col + 1];
            o2 += bias[col + 2]; o3 += bias[col + 3];
            int b = b_idx[row];
            const float* tpr = tp + b * 256;
            o0 = (1.f + tpr[col + 0]) * o0 + tpr[128 + col + 0];
            o1 = (1.f + tpr[col + 1]) * o1 + tpr[128 + col + 1];
            o2 = (1.f + tpr[col + 2]) * o2 + tpr[128 + col + 2];
            o3 = (1.f + tpr[col + 3]) * o3 + tpr[128 + col + 3];
        }
        *(float4*)(out + (size_t)row * NFW + col) = make_float4(o0, o1, o2, o3);
    }
}

// ---------------- launch ----------------
extern "C" void kernel_launch(void* const* d_in, const int* in_sizes, int n_in,
                              void* d_out, int out_size) {
    const float* x        = (const float*)d_in[0];
    const float* t        = (const float*)d_in[1];
    const int*   b_idx    = (const int*)d_in[2];
    const int*   nbr      = (const int*)d_in[3];
    const int*   nbr_down = (const int*)d_in[4];
    const float* g1       = (const float*)d_in[5];
    const float* be1      = (const float*)d_in[6];
    const float* W1       = (const float*)d_in[7];
    const float* b1       = (const float*)d_in[8];
    const float* Wt       = (const float*)d_in[9];
    const float* bt       = (const float*)d_in[10];
    const float* g2       = (const float*)d_in[11];
    const float* be2      = (const float*)d_in[12];
    const float* W2       = (const float*)d_in[13];
    const float* b2       = (const float*)d_in[14];
    const float* Wid      = (const float*)d_in[15];
    const float* bid      = (const float*)d_in[16];
    const float* Wd       = (const float*)d_in[17];
    float* out = (float*)d_out;

    float *pa, *ph, *ph2, *pstats, *pbn, *ptp;
    cudaGetSymbolAddress((void**)&pa, g_a);
    cudaGetSymbolAddress((void**)&ph, g_h);
    cudaGetSymbolAddress((void**)&ph2, g_h2);
    cudaGetSymbolAddress((void**)&pstats, g_stats);
    cudaGetSymbolAddress((void**)&pbn, g_bn);
    cudaGetSymbolAddress((void**)&ptp, g_tp);

    const int N = in_sizes[0] / 64;          // 200000
    const int K = in_sizes[3] / N;           // 27
    const int KD = in_sizes[17] / (128 * 128); // 8
    const int ND = in_sizes[4] / KD;         // 25000
    const float invN = 1.f / (float)N;

    const size_t sm64  = (64 * 64 + 32 * 128) * sizeof(float);   // 32 KB
    const size_t sm128 = (64 * 128 + 32 * 128) * sizeof(float);  // 48 KB

    // BN1 stats on x
    zero_stats_kernel<<<1, 384>>>(pstats);
    stats_kernel<64><<<512, 256>>>(x, N, pstats + 0, pstats + 64);
    finalize_bn_kernel<<<1, 64>>>(pstats + 0, pstats + 64, g1, be1, invN, 64, pbn + 0, pbn + 64);
    bnsilu_kernel<<<2048, 256>>>(x, pbn + 0, pbn + 64, (size_t)N * 64, 63, pa);

    // time embedding projection
    temb_kernel<<<16, 256>>>(t, Wt, bt, ptp);

    // conv1 (64 -> 128) with fused +b1 and time-embedding affine
    conv_kernel<64, 1, false><<<N / 64, 256, sm64>>>(pa, nbr, K, N, W1, b1, nullptr, ph, ptp, b_idx);

    // BN2 stats on h
    stats_kernel<128><<<512, 256>>>(ph, N, pstats + 128, pstats + 256);
    finalize_bn_kernel<<<1, 128>>>(pstats + 128, pstats + 256, g2, be2, invN, 128, pbn + 128, pbn + 256);
    bnsilu_kernel<<<2048, 256>>>(ph, pbn + 128, pbn + 256, (size_t)N * 128, 127, pa);

    // identity conv base: h2 = x @ Wid + bid + b2
    conv_kernel<64, 0, true><<<N / 64, 256, sm64>>>(x, nullptr, 1, N, Wid, bid, b2, ph2, nullptr, nullptr);

    // conv2 (128 -> 128) accumulated on top of h2
    conv_kernel<128, 2, false><<<N / 64, 256, sm128>>>(pa, nbr, K, N, W2, nullptr, nullptr, ph2, nullptr, nullptr);

    // strided down conv (8 taps) -> output [ND, 128]
    conv_kernel<128, 0, false><<<(ND + 63) / 64, 256, sm128>>>(ph2, nbr_down, KD, ND, Wd, nullptr, nullptr, out, nullptr, nullptr);
}

// round 5
// speedup vs baseline: 1.5899x; 1.5899x over previous
#include <cuda_runtime.h>
#include <cstdint>

#define N_VOX 200000
#define NFW 128
#define SA 68          // A stage row stride (floats)
#define SWX 68         // W stage row stride
#define SC 132         // C staging row stride
#define STG_F (128 * SA)               // 8704 floats per stage
#define SMEM_BYTES (6 * STG_F * 4)     // 3 A stages + 3 W stages = 208896 B

// ---------------- scratch (static device globals; no allocation) ----------------
__device__ float g_a[(size_t)N_VOX * 128];   // bnsilu outputs (column-permuted, tf32-rounded)
__device__ float g_h[(size_t)N_VOX * 128];   // conv1 output h (natural layout)
__device__ float g_h2[(size_t)N_VOX * 128];  // idconv + conv2 (column-permuted)
__device__ float g_stats[384];
__device__ float g_bn[384];
__device__ float g_tp[16 * 256];
__device__ float g_wt[802816];               // transposed+permuted weights

#define WT1_OFF 0
#define WT2_OFF (27 * 128 * 64)
#define WTD_OFF (WT2_OFF + 27 * 128 * 128)
#define WTID_OFF (WTD_OFF + 8 * 128 * 128)

// ---------------- helpers ----------------
__device__ __forceinline__ float silu_(float z) {
    return z * (1.f / (1.f + __expf(-z)));
}
__device__ __forceinline__ float to_tf32(float x) {
    float r;
    asm("cvt.rna.tf32.f32 %0, %1;" : "=f"(r) : "f"(x));
    return r;
}
__device__ __forceinline__ uint32_t smem_u32(const void* p) {
    uint32_t a;
    asm("{ .reg .u64 t; cvta.to.shared.u64 t, %1; cvt.u32.u64 %0, t; }" : "=r"(a) : "l"(p));
    return a;
}
__device__ __forceinline__ void cpasync16(uint32_t dst, const void* src, uint32_t sz) {
    asm volatile("cp.async.cg.shared.global [%0], [%1], 16, %2;"
                 :: "r"(dst), "l"(src), "r"(sz) : "memory");
}
#define CP_COMMIT() asm volatile("cp.async.commit_group;" ::: "memory")
#define CP_WAIT1()  asm volatile("cp.async.wait_group 1;" ::: "memory")

__device__ __forceinline__ void mma8(float* c, const uint32_t* a, uint32_t b0, uint32_t b1) {
    asm volatile(
        "mma.sync.aligned.m16n8k8.row.col.f32.tf32.tf32.f32 "
        "{%0,%1,%2,%3}, {%4,%5,%6,%7}, {%8,%9}, {%0,%1,%2,%3};"
        : "+f"(c[0]), "+f"(c[1]), "+f"(c[2]), "+f"(c[3])
        : "r"(a[0]), "r"(a[1]), "r"(a[2]), "r"(a[3]), "r"(b0), "r"(b1));
}

// inverse of the k-pair column permutation (within 8-groups)
__device__ __forceinline__ int invp(int p) {
    return (p & ~7) | ((p & 1) << 2) | ((p >> 1) & 3);
}

// ---------------- small kernels ----------------
__global__ void zero_stats_kernel(float* stats) {
    if (threadIdx.x < 384) stats[threadIdx.x] = 0.f;
}

template <int C>
__global__ void stats_kernel(const float* __restrict__ X, int M,
                             float* __restrict__ gsum, float* __restrict__ gsq) {
    constexpr int RPB = 256 / C;
    const int c = threadIdx.x & (C - 1);
    const int rg = threadIdx.x / C;
    float s = 0.f, q = 0.f;
    for (int r = blockIdx.x * RPB + rg; r < M; r += gridDim.x * RPB) {
        float v = X[(size_t)r * C + c];
        s += v;
        q += v * v;
    }
    __shared__ float sh[256];
    __shared__ float sh2[256];
    sh[threadIdx.x] = s;
    sh2[threadIdx.x] = q;
    __syncthreads();
    if (threadIdx.x < C) {
        #pragma unroll
        for (int g = 1; g < RPB; ++g) {
            s += sh[g * C + c];
            q += sh2[g * C + c];
        }
        atomicAdd(&gsum[c], s);
        atomicAdd(&gsq[c], q);
    }
}

__global__ void finalize_bn_kernel(const float* __restrict__ gsum, const float* __restrict__ gsq,
                                   const float* __restrict__ g, const float* __restrict__ be,
                                   float invM, int C,
                                   float* __restrict__ oscale, float* __restrict__ obias) {
    int c = threadIdx.x;
    if (c < C) {
        float m = gsum[c] * invM;
        float v = gsq[c] * invM - m * m;
        float a = g[c] * rsqrtf(v + 1e-5f);
        oscale[c] = a;
        obias[c] = be[c] - m * a;
    }
}

// bnsilu with column permutation + tf32 rounding on output
__global__ void bnsilu_kernel(const float* __restrict__ X, const float* __restrict__ sc,
                              const float* __restrict__ bi, size_t total, int cmask,
                              float* __restrict__ out) {
    for (size_t i = (size_t)blockIdx.x * blockDim.x + threadIdx.x; i < total;
         i += (size_t)gridDim.x * blockDim.x) {
        int c = (int)(i & (size_t)cmask);
        float z = X[i] * sc[c] + bi[c];
        size_t pos = (i & ~(size_t)7) | (size_t)(((c & 3) << 1) | ((c >> 2) & 1));
        out[pos] = to_tf32(silu_(z));
    }
}

__global__ void temb_kernel(const float* __restrict__ t, const float* __restrict__ Wt,
                            const float* __restrict__ bt, float* __restrict__ tp) {
    __shared__ float st[256];
    const int b = blockIdx.x, j = threadIdx.x;
    float v = t[b * 256 + j];
    st[j] = silu_(v);
    __syncthreads();
    float acc = bt[j];
    #pragma unroll 8
    for (int e = 0; e < 256; ++e) acc += st[e] * Wt[e * 256 + j];
    tp[b * 256 + j] = acc;
}

// W[k][c][n] -> Wt[k][n][perm(c)] with tf32 rounding
__global__ void transpose_w_kernel(const float* __restrict__ W, float* __restrict__ Wt,
                                   int K, int CIN) {
    int total = K * CIN * 128;
    for (int i = blockIdx.x * blockDim.x + threadIdx.x; i < total;
         i += gridDim.x * blockDim.x) {
        int p = i % CIN;
        int n = (i / CIN) & 127;
        int k = i / (CIN * 128);
        int c = invp(p);
        Wt[i] = to_tf32(W[(k * CIN + c) * 128 + n]);
    }
}

// ---------------- mma.sync tf32 gathered sparse-conv GEMM ----------------
// 128-row x 128-col tile per CTA, 256 threads (8 warps as 4x2 of m32 x n64).
// MODE 0: + bias (+bias2); MODE 1: TE affine; MODE 2: + addend[row][pos]
template <int CIN, int MODE, bool IDENT, bool PERM_IN, bool PERM_OUT>
__global__ void __launch_bounds__(256, 1)
conv_mma(const float* __restrict__ A, const int* __restrict__ nbr,
         int K, int M, const float* __restrict__ Wt,
         const float* __restrict__ bias, const float* __restrict__ bias2,
         float* __restrict__ out, const float* __restrict__ addend,
         const float* __restrict__ tp, const int* __restrict__ b_idx) {
    extern __shared__ float sm[];
    float* Ast = sm;
    float* Wst = sm + 3 * STG_F;
    float* Cs = sm;  // reused after mainloop
    const uint32_t uA = smem_u32(Ast);
    const uint32_t uW = smem_u32(Wst);

    const int tid = threadIdx.x;
    const int wid = tid >> 5, lane = tid & 31;
    const int wr = wid & 3, wc = wid >> 2;   // m0=32*wr, n0=64*wc
    const int lr = lane >> 2, lp = lane & 3;
    const int tile = blockIdx.x * 128;

    constexpr int NCH = CIN / 64;
    const int NC = K * NCH;

    float acc[2][8][4];
    #pragma unroll
    for (int t = 0; t < 2; ++t)
        #pragma unroll
        for (int j = 0; j < 8; ++j)
            #pragma unroll
            for (int i = 0; i < 4; ++i) acc[t][j][i] = 0.f;

    // ---- async stage fill: each thread owns one half-row (8 cp.asyncs each) ----
    auto fill_async = [&](int ci) {
        const int k = ci / NCH;
        const int cc = (ci - k * NCH) * 64;
        const int st = ci % 3;
        {
            const int r = tid >> 1, j0 = (tid & 1) * 8;
            const int row = tile + r;
            int idx = -1;
            if (row < M) idx = IDENT ? row : __ldg(nbr + (size_t)k * M + row);
            const float* src = A + (size_t)(idx < 0 ? 0 : idx) * CIN + cc + j0 * 4;
            const uint32_t dst = uA + (uint32_t)(st * STG_F + r * SA + j0 * 4) * 4u;
            const uint32_t sz = idx >= 0 ? 16u : 0u;
            #pragma unroll
            for (int j = 0; j < 8; ++j) cpasync16(dst + 16u * j, src + 4 * j, sz);
        }
        {
            const int n = tid >> 1, j0 = (tid & 1) * 8;
            const float* src = Wt + ((size_t)k * 128 + n) * CIN + cc + j0 * 4;
            const uint32_t dst = uW + (uint32_t)(st * STG_F + n * SWX + j0 * 4) * 4u;
            #pragma unroll
            for (int j = 0; j < 8; ++j) cpasync16(dst + 16u * j, src + 4 * j, 16u);
        }
    };

    // ---- direct stage fill (unpermuted input -> permute on STS) ----
    auto fill_direct = [&](int ci) {
        const int k = ci / NCH;
        const int cc = (ci - k * NCH) * 64;
        #pragma unroll
        for (int u = 0; u < 8; ++u) {
            int s = tid + 256 * u;
            int r = s >> 4, j = s & 15;
            int row = tile + r;
            int idx = -1;
            if (row < M) idx = IDENT ? row : __ldg(nbr + (size_t)k * M + row);
            float4 v = make_float4(0.f, 0.f, 0.f, 0.f);
            if (idx >= 0) v = *(const float4*)(A + (size_t)idx * CIN + cc + j * 4);
            int cl = 4 * j;
            int base = r * SA + (cl & ~7) + (j & 1);
            Ast[base + 0] = to_tf32(v.x);
            Ast[base + 2] = to_tf32(v.y);
            Ast[base + 4] = to_tf32(v.z);
            Ast[base + 6] = to_tf32(v.w);
        }
        #pragma unroll
        for (int u = 0; u < 8; ++u) {
            int s = tid + 256 * u;
            int n = s >> 4, j = s & 15;
            float4 v = *(const float4*)(Wt + ((size_t)k * 128 + n) * CIN + cc + j * 4);
            *(float4*)(Wst + n * SWX + j * 4) = v;
        }
    };

    auto compute = [&](int st) {
        const float* As = Ast + (PERM_IN ? st * STG_F : 0);
        const float* Ws = Wst + (PERM_IN ? st * STG_F : 0);
        #pragma unroll
        for (int kb = 0; kb < 64; kb += 8) {
            uint32_t a[2][4];
            #pragma unroll
            for (int t = 0; t < 2; ++t) {
                const float* pa = As + (32 * wr + 16 * t + lr) * SA + kb + 2 * lp;
                float2 v01 = *(const float2*)pa;
                float2 v23 = *(const float2*)(pa + 8 * SA);
                a[t][0] = __float_as_uint(v01.x);
                a[t][2] = __float_as_uint(v01.y);
                a[t][1] = __float_as_uint(v23.x);
                a[t][3] = __float_as_uint(v23.y);
            }
            #pragma unroll
            for (int j = 0; j < 8; ++j) {
                const float* pb = Ws + (64 * wc + 8 * j + lr) * SWX + kb + 2 * lp;
                float2 b = *(const float2*)pb;
                uint32_t b0 = __float_as_uint(b.x), b1 = __float_as_uint(b.y);
                mma8(acc[0][j], a[0], b0, b1);
                mma8(acc[1][j], a[1], b0, b1);
            }
        }
    };

    if (PERM_IN) {
        fill_async(0);
        CP_COMMIT();
        if (NC > 1) { fill_async(1); }
        CP_COMMIT();
        for (int ci = 0; ci < NC; ++ci) {
            CP_WAIT1();
            __syncthreads();
            compute(ci % 3);
            __syncthreads();
            if (ci + 2 < NC) fill_async(ci + 2);
            CP_COMMIT();
        }
    } else {
        for (int ci = 0; ci < NC; ++ci) {
            __syncthreads();
            fill_direct(ci);
            __syncthreads();
            compute(0);
        }
    }

    // ---- stage C through smem for coalesced stores ----
    __syncthreads();
    #pragma unroll
    for (int t = 0; t < 2; ++t)
        #pragma unroll
        for (int j = 0; j < 8; ++j) {
            int r0 = 32 * wr + 16 * t + lr;
            int cc0 = 64 * wc + 8 * j + 2 * lp;
            *(float2*)&Cs[r0 * SC + cc0] = make_float2(acc[t][j][0], acc[t][j][1]);
            *(float2*)&Cs[(r0 + 8) * SC + cc0] = make_float2(acc[t][j][2], acc[t][j][3]);
        }
    __syncthreads();

    // ---- epilogue: thread -> (row, half) ----
    const int r = tid >> 1;
    const int hf = tid & 1;
    const int row = tile + r;
    if (row < M) {
        const float* tpr = nullptr;
        if (MODE == 1) tpr = tp + b_idx[row] * 256;
        #pragma unroll 4
        for (int q = 0; q < 16; ++q) {
            const int p0 = hf * 64 + q * 4;
            float v[4];
            int f[4];
            #pragma unroll
            for (int i = 0; i < 4; ++i) {
                f[i] = PERM_OUT ? invp(p0 + i) : (p0 + i);
                v[i] = Cs[r * SC + f[i]];
            }
            float4 ad;
            if (MODE == 2) ad = *(const float4*)(addend + (size_t)row * NFW + p0);
            #pragma unroll
            for (int i = 0; i < 4; ++i) {
                if (MODE == 0) {
                    if (bias) v[i] += bias[f[i]];
                    if (bias2) v[i] += bias2[f[i]];
                } else if (MODE == 1) {
                    v[i] = (1.f + tpr[f[i]]) * (v[i] + bias[f[i]]) + tpr[128 + f[i]];
                } else {
                    v[i] += (&ad.x)[i];
                }
            }
            *(float4*)(out + (size_t)row * NFW + p0) = make_float4(v[0], v[1], v[2], v[3]);
        }
    }
}

// ---------------- launch ----------------
extern "C" void kernel_launch(void* const* d_in, const int* in_sizes, int n_in,
                              void* d_out, int out_size) {
    const float* x        = (const float*)d_in[0];
    const float* t        = (const float*)d_in[1];
    const int*   b_idx    = (const int*)d_in[2];
    const int*   nbr      = (const int*)d_in[3];
    const int*   nbr_down = (const int*)d_in[4];
    const float* g1       = (const float*)d_in[5];
    const float* be1      = (const float*)d_in[6];
    const float* W1       = (const float*)d_in[7];
    const float* b1       = (const float*)d_in[8];
    const float* Wt       = (const float*)d_in[9];
    const float* bt       = (const float*)d_in[10];
    const float* g2       = (const float*)d_in[11];
    const float* be2      = (const float*)d_in[12];
    const float* W2       = (const float*)d_in[13];
    const float* b2       = (const float*)d_in[14];
    const float* Wid      = (const float*)d_in[15];
    const float* bid      = (const float*)d_in[16];
    const float* Wd       = (const float*)d_in[17];
    float* out = (float*)d_out;

    float *pa, *ph, *ph2, *pstats, *pbn, *ptp, *pwt;
    cudaGetSymbolAddress((void**)&pa, g_a);
    cudaGetSymbolAddress((void**)&ph, g_h);
    cudaGetSymbolAddress((void**)&ph2, g_h2);
    cudaGetSymbolAddress((void**)&pstats, g_stats);
    cudaGetSymbolAddress((void**)&pbn, g_bn);
    cudaGetSymbolAddress((void**)&ptp, g_tp);
    cudaGetSymbolAddress((void**)&pwt, g_wt);

    cudaFuncSetAttribute(conv_mma<64, 1, false, true, false>,
                         cudaFuncAttributeMaxDynamicSharedMemorySize, SMEM_BYTES);
    cudaFuncSetAttribute(conv_mma<64, 0, true, false, true>,
                         cudaFuncAttributeMaxDynamicSharedMemorySize, SMEM_BYTES);
    cudaFuncSetAttribute(conv_mma<128, 2, false, true, true>,
                         cudaFuncAttributeMaxDynamicSharedMemorySize, SMEM_BYTES);
    cudaFuncSetAttribute(conv_mma<128, 0, false, true, false>,
                         cudaFuncAttributeMaxDynamicSharedMemorySize, SMEM_BYTES);

    const int N = in_sizes[0] / 64;             // 200000
    const int K = in_sizes[3] / N;              // 27
    const int KD = in_sizes[17] / (128 * 128);  // 8
    const int ND = in_sizes[4] / KD;            // 25000
    const float invN = 1.f / (float)N;
    const int GN = (N + 127) / 128;
    const int GD = (ND + 127) / 128;

    // weight transpose + permute + tf32 round
    transpose_w_kernel<<<216, 256>>>(W1, pwt + WT1_OFF, K, 64);
    transpose_w_kernel<<<432, 256>>>(W2, pwt + WT2_OFF, K, 128);
    transpose_w_kernel<<<128, 256>>>(Wd, pwt + WTD_OFF, KD, 128);
    transpose_w_kernel<<<32, 256>>>(Wid, pwt + WTID_OFF, 1, 64);

    // BN1 stats + bnsilu(x) -> g_a (permuted, tf32)
    zero_stats_kernel<<<1, 384>>>(pstats);
    stats_kernel<64><<<512, 256>>>(x, N, pstats + 0, pstats + 64);
    finalize_bn_kernel<<<1, 64>>>(pstats + 0, pstats + 64, g1, be1, invN, 64, pbn + 0, pbn + 64);
    bnsilu_kernel<<<2048, 256>>>(x, pbn + 0, pbn + 64, (size_t)N * 64, 63, pa);

    temb_kernel<<<16, 256>>>(t, Wt, bt, ptp);

    // conv1 (64->128) + b1 + TE affine -> g_h (natural)
    conv_mma<64, 1, false, true, false><<<GN, 256, SMEM_BYTES>>>(
        pa, nbr, K, N, pwt + WT1_OFF, b1, nullptr, ph, nullptr, ptp, b_idx);

    // BN2 stats + bnsilu(h) -> g_a (permuted, tf32)
    stats_kernel<128><<<512, 256>>>(ph, N, pstats + 128, pstats + 256);
    finalize_bn_kernel<<<1, 128>>>(pstats + 128, pstats + 256, g2, be2, invN, 128,
                                   pbn + 128, pbn + 256);
    bnsilu_kernel<<<2048, 256>>>(ph, pbn + 128, pbn + 256, (size_t)N * 128, 127, pa);

    // idconv: h2 = x @ Wid + bid + b2  (output permuted)
    conv_mma<64, 0, true, false, true><<<GN, 256, SMEM_BYTES>>>(
        x, nullptr, 1, N, pwt + WTID_OFF, bid, b2, ph2, nullptr, nullptr, nullptr);

    // conv2 (128->128) + h2 addend -> g_h2 (permuted)
    conv_mma<128, 2, false, true, true><<<GN, 256, SMEM_BYTES>>>(
        pa, nbr, K, N, pwt + WT2_OFF, nullptr, nullptr, ph2, ph2, nullptr, nullptr);

    // strided down conv (8 taps) -> out [ND, 128] (natural)
    conv_mma<128, 0, false, true, false><<<GD, 256, SMEM_BYTES>>>(
        ph2, nbr_down, KD, ND, pwt + WTD_OFF, nullptr, nullptr, out, nullptr, nullptr, nullptr);
}

// round 6
// speedup vs baseline: 1.9172x; 1.2059x over previous
#include <cuda_runtime.h>
#include <cstdint>

#define N_VOX 200000
#define NFW 128
#define SA 72            // A stage row stride (floats): 72 % 32 == 8 -> conflict-free
#define SWX 72           // W stage row stride
#define SC 136           // C staging row stride
#define A_STG (256 * SA)               // 18432 floats
#define W_STG (128 * SWX)              // 9216 floats
#define SMEM_BYTES ((2 * A_STG + 2 * W_STG) * 4)   // 221184 B

// ---------------- scratch (static device globals; no allocation) ----------------
__device__ float g_a[(size_t)N_VOX * 128];   // bnsilu outputs (column-permuted, tf32-rounded)
__device__ float g_h[(size_t)N_VOX * 128];   // conv1 output h (natural layout)
__device__ float g_h2[(size_t)N_VOX * 128];  // idconv + conv2 (column-permuted)
__device__ float g_stats[384];
__device__ float g_bn[384];
__device__ float g_tp[16 * 256];
__device__ float g_wt[802816];               // transposed+permuted weights

#define WT1_OFF 0
#define WT2_OFF (27 * 128 * 64)
#define WTD_OFF (WT2_OFF + 27 * 128 * 128)
#define WTID_OFF (WTD_OFF + 8 * 128 * 128)

// ---------------- helpers ----------------
__device__ __forceinline__ float silu_(float z) {
    return z * (1.f / (1.f + __expf(-z)));
}
__device__ __forceinline__ float to_tf32(float x) {
    float r;
    asm("cvt.rna.tf32.f32 %0, %1;" : "=f"(r) : "f"(x));
    return r;
}
__device__ __forceinline__ uint32_t smem_u32(const void* p) {
    uint32_t a;
    asm("{ .reg .u64 t; cvta.to.shared.u64 t, %1; cvt.u32.u64 %0, t; }" : "=r"(a) : "l"(p));
    return a;
}
__device__ __forceinline__ void cpasync16(uint32_t dst, const void* src, uint32_t sz) {
    asm volatile("cp.async.cg.shared.global [%0], [%1], 16, %2;"
                 :: "r"(dst), "l"(src), "r"(sz) : "memory");
}
#define CP_COMMIT() asm volatile("cp.async.commit_group;" ::: "memory")
#define CP_WAIT1()  asm volatile("cp.async.wait_group 1;" ::: "memory")

__device__ __forceinline__ void mma8(float* c, const uint32_t* a, uint32_t b0, uint32_t b1) {
    asm volatile(
        "mma.sync.aligned.m16n8k8.row.col.f32.tf32.tf32.f32 "
        "{%0,%1,%2,%3}, {%4,%5,%6,%7}, {%8,%9}, {%0,%1,%2,%3};"
        : "+f"(c[0]), "+f"(c[1]), "+f"(c[2]), "+f"(c[3])
        : "r"(a[0]), "r"(a[1]), "r"(a[2]), "r"(a[3]), "r"(b0), "r"(b1));
}

// inverse of the k-pair column permutation (within 8-groups)
__device__ __forceinline__ int invp(int p) {
    return (p & ~7) | ((p & 1) << 2) | ((p >> 1) & 3);
}

// ---------------- small kernels ----------------
__global__ void zero_stats_kernel(float* stats) {
    if (threadIdx.x < 384) stats[threadIdx.x] = 0.f;
}

template <int C>
__global__ void stats_kernel(const float* __restrict__ X, int M,
                             float* __restrict__ gsum, float* __restrict__ gsq) {
    constexpr int RPB = 256 / C;
    const int c = threadIdx.x & (C - 1);
    const int rg = threadIdx.x / C;
    float s = 0.f, q = 0.f;
    for (int r = blockIdx.x * RPB + rg; r < M; r += gridDim.x * RPB) {
        float v = X[(size_t)r * C + c];
        s += v;
        q += v * v;
    }
    __shared__ float sh[256];
    __shared__ float sh2[256];
    sh[threadIdx.x] = s;
    sh2[threadIdx.x] = q;
    __syncthreads();
    if (threadIdx.x < C) {
        #pragma unroll
        for (int g = 1; g < RPB; ++g) {
            s += sh[g * C + c];
            q += sh2[g * C + c];
        }
        atomicAdd(&gsum[c], s);
        atomicAdd(&gsq[c], q);
    }
}

__global__ void finalize_bn_kernel(const float* __restrict__ gsum, const float* __restrict__ gsq,
                                   const float* __restrict__ g, const float* __restrict__ be,
                                   float invM, int C,
                                   float* __restrict__ oscale, float* __restrict__ obias) {
    int c = threadIdx.x;
    if (c < C) {
        float m = gsum[c] * invM;
        float v = gsq[c] * invM - m * m;
        float a = g[c] * rsqrtf(v + 1e-5f);
        oscale[c] = a;
        obias[c] = be[c] - m * a;
    }
}

// bnsilu with column permutation + tf32 rounding on output
__global__ void bnsilu_kernel(const float* __restrict__ X, const float* __restrict__ sc,
                              const float* __restrict__ bi, size_t total, int cmask,
                              float* __restrict__ out) {
    for (size_t i = (size_t)blockIdx.x * blockDim.x + threadIdx.x; i < total;
         i += (size_t)gridDim.x * blockDim.x) {
        int c = (int)(i & (size_t)cmask);
        float z = X[i] * sc[c] + bi[c];
        size_t pos = (i & ~(size_t)7) | (size_t)(((c & 3) << 1) | ((c >> 2) & 1));
        out[pos] = to_tf32(silu_(z));
    }
}

__global__ void temb_kernel(const float* __restrict__ t, const float* __restrict__ Wt,
                            const float* __restrict__ bt, float* __restrict__ tp) {
    __shared__ float st[256];
    const int b = blockIdx.x, j = threadIdx.x;
    float v = t[b * 256 + j];
    st[j] = silu_(v);
    __syncthreads();
    float acc = bt[j];
    #pragma unroll 8
    for (int e = 0; e < 256; ++e) acc += st[e] * Wt[e * 256 + j];
    tp[b * 256 + j] = acc;
}

// W[k][c][n] -> Wt[k][n][perm(c)] with tf32 rounding
__global__ void transpose_w_kernel(const float* __restrict__ W, float* __restrict__ Wt,
                                   int K, int CIN) {
    int total = K * CIN * 128;
    for (int i = blockIdx.x * blockDim.x + threadIdx.x; i < total;
         i += gridDim.x * blockDim.x) {
        int p = i % CIN;
        int n = (i / CIN) & 127;
        int k = i / (CIN * 128);
        int c = invp(p);
        Wt[i] = to_tf32(W[(k * CIN + c) * 128 + n]);
    }
}

// ---------------- mma.sync tf32 gathered sparse-conv GEMM ----------------
// 256-row x 128-col tile per CTA, 256 threads (8 warps as 4m x 2n of m64 x n64).
// MODE 0: + bias (+bias2); MODE 1: TE affine; MODE 2: + addend[row][pos]
template <int CIN, int MODE, bool IDENT, bool PERM_IN, bool PERM_OUT>
__global__ void __launch_bounds__(256, 1)
conv_mma(const float* __restrict__ A, const int* __restrict__ nbr,
         int K, int M, const float* __restrict__ Wt,
         const float* __restrict__ bias, const float* __restrict__ bias2,
         float* __restrict__ out, const float* __restrict__ addend,
         const float* __restrict__ tp, const int* __restrict__ b_idx) {
    extern __shared__ float sm[];
    float* Ast = sm;
    float* Wst = sm + 2 * A_STG;
    float* Cs = sm;  // reused after mainloop
    const uint32_t uA = smem_u32(Ast);
    const uint32_t uW = smem_u32(Wst);

    const int tid = threadIdx.x;
    const int wid = tid >> 5, lane = tid & 31;
    const int wr = wid & 3, wc = wid >> 2;   // m0=64*wr, n0=64*wc
    const int lr = lane >> 2, lp = lane & 3;
    const int tile = blockIdx.x * 256;

    constexpr int NCH = CIN / 64;
    const int NC = K * NCH;

    float acc[4][8][4];
    #pragma unroll
    for (int t = 0; t < 4; ++t)
        #pragma unroll
        for (int j = 0; j < 8; ++j)
            #pragma unroll
            for (int i = 0; i < 4; ++i) acc[t][j][i] = 0.f;

    // ---- async stage fill: thread owns one full A row (16 cp.asyncs, 1 nbr load) ----
    auto fill_async = [&](int ci) {
        const int k = ci / NCH;
        const int cc = (ci - k * NCH) * 64;
        const int st = ci & 1;
        {
            const int r = tid;
            const int row = tile + r;
            int idx = -1;
            if (row < M) idx = IDENT ? row : __ldg(nbr + (size_t)k * M + row);
            const float* src = A + (size_t)(idx < 0 ? 0 : idx) * CIN + cc;
            const uint32_t dst = uA + (uint32_t)(st * A_STG + r * SA) * 4u;
            const uint32_t sz = idx >= 0 ? 16u : 0u;
            #pragma unroll
            for (int j = 0; j < 16; ++j) cpasync16(dst + 16u * j, src + 4 * j, sz);
        }
        {
            const int n = tid >> 1, j0 = (tid & 1) * 8;
            const float* src = Wt + ((size_t)k * 128 + n) * CIN + cc + j0 * 4;
            const uint32_t dst = uW + (uint32_t)(st * W_STG + n * SWX + j0 * 4) * 4u;
            #pragma unroll
            for (int j = 0; j < 8; ++j) cpasync16(dst + 16u * j, src + 4 * j, 16u);
        }
    };

    // ---- direct stage fill (unpermuted input -> permute on STS; NC==1 path) ----
    auto fill_direct = [&](int ci) {
        const int k = ci / NCH;
        const int cc = (ci - k * NCH) * 64;
        #pragma unroll
        for (int u = 0; u < 16; ++u) {
            int s = tid + 256 * u;
            int r = s >> 4, j = s & 15;
            int row = tile + r;
            int idx = -1;
            if (row < M) idx = IDENT ? row : __ldg(nbr + (size_t)k * M + row);
            float4 v = make_float4(0.f, 0.f, 0.f, 0.f);
            if (idx >= 0) v = *(const float4*)(A + (size_t)idx * CIN + cc + j * 4);
            int cl = 4 * j;
            int base = r * SA + (cl & ~7) + (j & 1);
            Ast[base + 0] = to_tf32(v.x);
            Ast[base + 2] = to_tf32(v.y);
            Ast[base + 4] = to_tf32(v.z);
            Ast[base + 6] = to_tf32(v.w);
        }
        #pragma unroll
        for (int u = 0; u < 8; ++u) {
            int s = tid + 256 * u;
            int n = s >> 4, j = s & 15;
            float4 v = *(const float4*)(Wt + ((size_t)k * 128 + n) * CIN + cc + j * 4);
            *(float4*)(Wst + n * SWX + j * 4) = v;
        }
    };

    auto compute = [&](int st) {
        const float* As = Ast + (PERM_IN ? st * A_STG : 0);
        const float* Ws = Wst + (PERM_IN ? st * W_STG : 0);
        #pragma unroll
        for (int kb = 0; kb < 64; kb += 8) {
            uint32_t a[4][4];
            #pragma unroll
            for (int t = 0; t < 4; ++t) {
                const float* pa = As + (64 * wr + 16 * t + lr) * SA + kb + 2 * lp;
                float2 v01 = *(const float2*)pa;
                float2 v23 = *(const float2*)(pa + 8 * SA);
                a[t][0] = __float_as_uint(v01.x);
                a[t][2] = __float_as_uint(v01.y);
                a[t][1] = __float_as_uint(v23.x);
                a[t][3] = __float_as_uint(v23.y);
            }
            #pragma unroll
            for (int j = 0; j < 8; ++j) {
                const float* pb = Ws + (64 * wc + 8 * j + lr) * SWX + kb + 2 * lp;
                float2 b = *(const float2*)pb;
                uint32_t b0 = __float_as_uint(b.x), b1 = __float_as_uint(b.y);
                #pragma unroll
                for (int t = 0; t < 4; ++t) mma8(acc[t][j], a[t], b0, b1);
            }
        }
    };

    if (PERM_IN) {
        fill_async(0);
        CP_COMMIT();
        if (NC > 1) { fill_async(1); }
        CP_COMMIT();
        for (int ci = 0; ci < NC; ++ci) {
            CP_WAIT1();
            __syncthreads();
            compute(ci & 1);
            __syncthreads();
            if (ci + 2 < NC) fill_async(ci + 2);
            CP_COMMIT();
        }
    } else {
        for (int ci = 0; ci < NC; ++ci) {
            __syncthreads();
            fill_direct(ci);
            __syncthreads();
            compute(0);
        }
    }

    // ---- stage C through smem for coalesced stores ----
    __syncthreads();
    #pragma unroll
    for (int t = 0; t < 4; ++t)
        #pragma unroll
        for (int j = 0; j < 8; ++j) {
            int r0 = 64 * wr + 16 * t + lr;
            int cc0 = 64 * wc + 8 * j + 2 * lp;
            *(float2*)&Cs[r0 * SC + cc0] = make_float2(acc[t][j][0], acc[t][j][1]);
            *(float2*)&Cs[(r0 + 8) * SC + cc0] = make_float2(acc[t][j][2], acc[t][j][3]);
        }
    __syncthreads();

    // ---- epilogue: thread -> row ----
    const int r = tid;
    const int row = tile + r;
    if (row < M) {
        const float* tpr = nullptr;
        if (MODE == 1) tpr = tp + b_idx[row] * 256;
        #pragma unroll 4
        for (int q = 0; q < 32; ++q) {
            const int p0 = q * 4;
            float v[4];
            int f[4];
            #pragma unroll
            for (int i = 0; i < 4; ++i) {
                f[i] = PERM_OUT ? invp(p0 + i) : (p0 + i);
                v[i] = Cs[r * SC + f[i]];
            }
            float4 ad;
            if (MODE == 2) ad = *(const float4*)(addend + (size_t)row * NFW + p0);
            #pragma unroll
            for (int i = 0; i < 4; ++i) {
                if (MODE == 0) {
                    if (bias) v[i] += bias[f[i]];
                    if (bias2) v[i] += bias2[f[i]];
                } else if (MODE == 1) {
                    v[i] = (1.f + tpr[f[i]]) * (v[i] + bias[f[i]]) + tpr[128 + f[i]];
                } else {
                    v[i] += (&ad.x)[i];
                }
            }
            *(float4*)(out + (size_t)row * NFW + p0) = make_float4(v[0], v[1], v[2], v[3]);
        }
    }
}

// ---------------- launch ----------------
extern "C" void kernel_launch(void* const* d_in, const int* in_sizes, int n_in,
                              void* d_out, int out_size) {
    const float* x        = (const float*)d_in[0];
    const float* t        = (const float*)d_in[1];
    const int*   b_idx    = (const int*)d_in[2];
    const int*   nbr      = (const int*)d_in[3];
    const int*   nbr_down = (const int*)d_in[4];
    const float* g1       = (const float*)d_in[5];
    const float* be1      = (const float*)d_in[6];
    const float* W1       = (const float*)d_in[7];
    const float* b1       = (const float*)d_in[8];
    const float* Wt       = (const float*)d_in[9];
    const float* bt       = (const float*)d_in[10];
    const float* g2       = (const float*)d_in[11];
    const float* be2      = (const float*)d_in[12];
    const float* W2       = (const float*)d_in[13];
    const float* b2       = (const float*)d_in[14];
    const float* Wid      = (const float*)d_in[15];
    const float* bid      = (const float*)d_in[16];
    const float* Wd       = (const float*)d_in[17];
    float* out = (float*)d_out;

    float *pa, *ph, *ph2, *pstats, *pbn, *ptp, *pwt;
    cudaGetSymbolAddress((void**)&pa, g_a);
    cudaGetSymbolAddress((void**)&ph, g_h);
    cudaGetSymbolAddress((void**)&ph2, g_h2);
    cudaGetSymbolAddress((void**)&pstats, g_stats);
    cudaGetSymbolAddress((void**)&pbn, g_bn);
    cudaGetSymbolAddress((void**)&ptp, g_tp);
    cudaGetSymbolAddress((void**)&pwt, g_wt);

    cudaFuncSetAttribute(conv_mma<64, 1, false, true, false>,
                         cudaFuncAttributeMaxDynamicSharedMemorySize, SMEM_BYTES);
    cudaFuncSetAttribute(conv_mma<64, 0, true, false, true>,
                         cudaFuncAttributeMaxDynamicSharedMemorySize, SMEM_BYTES);
    cudaFuncSetAttribute(conv_mma<128, 2, false, true, true>,
                         cudaFuncAttributeMaxDynamicSharedMemorySize, SMEM_BYTES);
    cudaFuncSetAttribute(conv_mma<128, 0, false, true, false>,
                         cudaFuncAttributeMaxDynamicSharedMemorySize, SMEM_BYTES);

    const int N = in_sizes[0] / 64;             // 200000
    const int K = in_sizes[3] / N;              // 27
    const int KD = in_sizes[17] / (128 * 128);  // 8
    const int ND = in_sizes[4] / KD;            // 25000
    const float invN = 1.f / (float)N;
    const int GN = (N + 255) / 256;
    const int GD = (ND + 255) / 256;

    // weight transpose + permute + tf32 round
    transpose_w_kernel<<<216, 256>>>(W1, pwt + WT1_OFF, K, 64);
    transpose_w_kernel<<<432, 256>>>(W2, pwt + WT2_OFF, K, 128);
    transpose_w_kernel<<<128, 256>>>(Wd, pwt + WTD_OFF, KD, 128);
    transpose_w_kernel<<<32, 256>>>(Wid, pwt + WTID_OFF, 1, 64);

    // BN1 stats + bnsilu(x) -> g_a (permuted, tf32)
    zero_stats_kernel<<<1, 384>>>(pstats);
    stats_kernel<64><<<512, 256>>>(x, N, pstats + 0, pstats + 64);
    finalize_bn_kernel<<<1, 64>>>(pstats + 0, pstats + 64, g1, be1, invN, 64, pbn + 0, pbn + 64);
    bnsilu_kernel<<<2048, 256>>>(x, pbn + 0, pbn + 64, (size_t)N * 64, 63, pa);

    temb_kernel<<<16, 256>>>(t, Wt, bt, ptp);

    // conv1 (64->128) + b1 + TE affine -> g_h (natural)
    conv_mma<64, 1, false, true, false><<<GN, 256, SMEM_BYTES>>>(
        pa, nbr, K, N, pwt + WT1_OFF, b1, nullptr, ph, nullptr, ptp, b_idx);

    // BN2 stats + bnsilu(h) -> g_a (permuted, tf32)
    stats_kernel<128><<<512, 256>>>(ph, N, pstats + 128, pstats + 256);
    finalize_bn_kernel<<<1, 128>>>(pstats + 128, pstats + 256, g2, be2, invN, 128,
                                   pbn + 128, pbn + 256);
    bnsilu_kernel<<<2048, 256>>>(ph, pbn + 128, pbn + 256, (size_t)N * 128, 127, pa);

    // idconv: h2 = x @ Wid + bid + b2  (output permuted)
    conv_mma<64, 0, true, false, true><<<GN, 256, SMEM_BYTES>>>(
        x, nullptr, 1, N, pwt + WTID_OFF, bid, b2, ph2, nullptr, nullptr, nullptr);

    // conv2 (128->128) + h2 addend -> g_h2 (permuted)
    conv_mma<128, 2, false, true, true><<<GN, 256, SMEM_BYTES>>>(
        pa, nbr, K, N, pwt + WT2_OFF, nullptr, nullptr, ph2, ph2, nullptr, nullptr);

    // strided down conv (8 taps) -> out [ND, 128] (natural)
    conv_mma<128, 0, false, true, false><<<GD, 256, SMEM_BYTES>>>(
        ph2, nbr_down, KD, ND, pwt + WTD_OFF, nullptr, nullptr, out, nullptr, nullptr, nullptr);
}

// round 8
// speedup vs baseline: 3.1614x; 1.6490x over previous
#include <cuda_runtime.h>
#include <cuda_fp16.h>
#include <cstdint>

#define N_VOX 200000
#define NFW 128
#define SAH 80           // A stage row stride (halves): 160B == 32 mod 128 -> conflict-free frags
#define SWH 80           // W stage row stride (halves)
#define SC 136           // C staging row stride (floats): 8 mod 32 -> conflict-free writes
#define A_STG (256 * SAH)              // 20480 halves
#define W_STG (128 * SWH)              // 10240 halves
#define SMEM_BYTES 139264              // max(2*(A_STG+W_STG)*2 = 122880, 256*SC*4 = 139264)

// ---------------- scratch (static device globals; no allocation) ----------------
__device__ __half g_a[(size_t)N_VOX * 128];  // f16 k-permuted activations (bnsilu / h2)
__device__ float g_h[(size_t)N_VOX * 128];   // conv1 output h (f32 natural)
__device__ float g_h2[(size_t)N_VOX * 128];  // idconv + conv2 output (f32 natural)
__device__ float g_stats[384];
__device__ float g_bn[384];
__device__ float g_tp[16 * 256];
__device__ __half g_wt[802816];              // transposed + k-permuted f16 weights

#define WT1_OFF 0
#define WT2_OFF (27 * 128 * 64)
#define WTD_OFF (WT2_OFF + 27 * 128 * 128)
#define WTID_OFF (WTD_OFF + 8 * 128 * 128)

// k-permutation within each 16-group: k=2p+e -> pos = 4*(p&3) + 2*(p>>2) + e
// (makes {2lp,2lp+1,2lp+8,2lp+9} an 8-byte contiguous run at offset 8*lp)

// ---------------- helpers ----------------
__device__ __forceinline__ float silu_(float z) {
    return z * (1.f / (1.f + __expf(-z)));
}
__device__ __forceinline__ uint32_t smem_u32(const void* p) {
    uint32_t a;
    asm("{ .reg .u64 t; cvta.to.shared.u64 t, %1; cvt.u32.u64 %0, t; }" : "=r"(a) : "l"(p));
    return a;
}
__device__ __forceinline__ void cpasync16(uint32_t dst, const void* src, uint32_t sz) {
    asm volatile("cp.async.cg.shared.global [%0], [%1], 16, %2;"
                 :: "r"(dst), "l"(src), "r"(sz) : "memory");
}
#define CP_COMMIT() asm volatile("cp.async.commit_group;" ::: "memory")
#define CP_WAIT1()  asm volatile("cp.async.wait_group 1;" ::: "memory")

__device__ __forceinline__ void mma16(float* c, const uint32_t* a, uint32_t b0, uint32_t b1) {
    asm volatile(
        "mma.sync.aligned.m16n8k16.row.col.f32.f16.f16.f32 "
        "{%0,%1,%2,%3}, {%4,%5,%6,%7}, {%8,%9}, {%0,%1,%2,%3};"
        : "+f"(c[0]), "+f"(c[1]), "+f"(c[2]), "+f"(c[3])
        : "r"(a[0]), "r"(a[1]), "r"(a[2]), "r"(a[3]), "r"(b0), "r"(b1));
}

// ---------------- small kernels ----------------
template <int C>
__global__ void stats_kernel(const float* __restrict__ X, int M,
                             float* __restrict__ gsum, float* __restrict__ gsq) {
    constexpr int RPB = 256 / C;
    const int c = threadIdx.x & (C - 1);
    const int rg = threadIdx.x / C;
    float s = 0.f, q = 0.f;
    for (int r = blockIdx.x * RPB + rg; r < M; r += gridDim.x * RPB) {
        float v = X[(size_t)r * C + c];
        s += v;
        q += v * v;
    }
    __shared__ float sh[256];
    __shared__ float sh2[256];
    sh[threadIdx.x] = s;
    sh2[threadIdx.x] = q;
    __syncthreads();
    if (threadIdx.x < C) {
        #pragma unroll
        for (int g = 1; g < RPB; ++g) {
            s += sh[g * C + c];
            q += sh2[g * C + c];
        }
        atomicAdd(&gsum[c], s);
        atomicAdd(&gsq[c], q);
    }
}

__global__ void finalize_bn_kernel(const float* __restrict__ gsum, const float* __restrict__ gsq,
                                   const float* __restrict__ g, const float* __restrict__ be,
                                   float invM, int C,
                                   float* __restrict__ oscale, float* __restrict__ obias) {
    int c = threadIdx.x;
    if (c < C) {
        float m = gsum[c] * invM;
        float v = gsq[c] * invM - m * m;
        float a = g[c] * rsqrtf(v + 1e-5f);
        oscale[c] = a;
        obias[c] = be[c] - m * a;
    }
}

// bnsilu -> f16 with k-permutation within 16-groups
__global__ void bnsilu_kernel(const float* __restrict__ X, const float* __restrict__ sc,
                              const float* __restrict__ bi, size_t total, int cmask,
                              __half* __restrict__ out) {
    for (size_t i = (size_t)blockIdx.x * blockDim.x + threadIdx.x; i < total;
         i += (size_t)gridDim.x * blockDim.x) {
        int c = (int)(i & (size_t)cmask);
        float z = X[i] * sc[c] + bi[c];
        int s = c & 15, p = s >> 1, e = s & 1;
        int pos = ((p & 3) << 2) | ((p >> 2) << 1) | e;
        out[(i & ~(size_t)15) | (size_t)pos] = __float2half_rn(silu_(z));
    }
}

// f32 natural -> f16 k-permuted (for downconv input)
__global__ void tohalf_kernel(const float* __restrict__ X, size_t total,
                              __half* __restrict__ out) {
    for (size_t i = (size_t)blockIdx.x * blockDim.x + threadIdx.x; i < total;
         i += (size_t)gridDim.x * blockDim.x) {
        int s = (int)(i & 15), p = s >> 1, e = s & 1;
        int pos = ((p & 3) << 2) | ((p >> 2) << 1) | e;
        out[(i & ~(size_t)15) | (size_t)pos] = __float2half_rn(X[i]);
    }
}

__global__ void temb_kernel(const float* __restrict__ t, const float* __restrict__ Wt,
                            const float* __restrict__ bt, float* __restrict__ tp) {
    __shared__ float st[256];
    const int b = blockIdx.x, j = threadIdx.x;
    float v = t[b * 256 + j];
    st[j] = silu_(v);
    __syncthreads();
    float acc = bt[j];
    #pragma unroll 8
    for (int e = 0; e < 256; ++e) acc += st[e] * Wt[e * 256 + j];
    tp[b * 256 + j] = acc;
}

// W[k][c][n] -> Wt[k][n][permpos(c)] f16; optionally zero ALL 384 stats (block 0)
__global__ void transpose_w_kernel(const float* __restrict__ W, __half* __restrict__ Wt,
                                   int K, int CIN, float* stats_zero) {
    if (stats_zero && blockIdx.x == 0) {
        for (int z = threadIdx.x; z < 384; z += blockDim.x) stats_zero[z] = 0.f;
    }
    int total = K * CIN * 128;
    for (int i = blockIdx.x * blockDim.x + threadIdx.x; i < total;
         i += gridDim.x * blockDim.x) {
        int p = i % CIN;
        int n = (i / CIN) & 127;
        int k = i / (CIN * 128);
        int g = p >> 4, s = p & 15;
        int q = s >> 2, r = s & 3;
        int c = (g << 4) | (2 * (q + ((r >> 1) << 2)) + (r & 1));
        Wt[i] = __float2half_rn(W[(k * CIN + c) * 128 + n]);
    }
}

// ---------------- f16 m16n8k16 gathered sparse-conv GEMM ----------------
// 256-row x 128-col tile, 256 threads (8 warps = 4m x 2n of m64 x n64), f32 accum.
// MODE 0: + bias (+bias2); MODE 1: TE affine; MODE 2: + addend (f32)
template <int CIN, int MODE, bool IDENT, bool ASYNC>
__global__ void __launch_bounds__(256, 1)
conv_mma(const __half* __restrict__ Af, const float* __restrict__ Afull,
         const int* __restrict__ nbr, int K, int M,
         const __half* __restrict__ Wt,
         const float* __restrict__ bias, const float* __restrict__ bias2,
         float* __restrict__ out, const float* __restrict__ addend,
         const float* __restrict__ tp, const int* __restrict__ b_idx) {
    extern __shared__ char smraw[];
    __half* Ast = (__half*)smraw;
    __half* Wst = Ast + 2 * A_STG;
    float* Cs = (float*)smraw;  // reused after mainloop
    const uint32_t uA = smem_u32(Ast);
    const uint32_t uW = smem_u32(Wst);

    const int tid = threadIdx.x;
    const int wid = tid >> 5, lane = tid & 31;
    const int wr = wid & 3, wc = wid >> 2;   // m0=64*wr, n0=64*wc
    const int lr = lane >> 2, lp = lane & 3;
    const int tile = blockIdx.x * 256;

    constexpr int NCH = CIN / 64;
    const int NC = K * NCH;

    float acc[4][8][4];
    #pragma unroll
    for (int t = 0; t < 4; ++t)
        #pragma unroll
        for (int j = 0; j < 8; ++j)
            #pragma unroll
            for (int i = 0; i < 4; ++i) acc[t][j][i] = 0.f;

    // ---- async fill from f16-permuted source ----
    auto fill_async = [&](int ci) {
        const int k = ci / NCH;
        const int cc = (ci - k * NCH) * 64;
        const int st = ci & 1;
        {
            const int r = tid;
            const int row = tile + r;
            int idx = row < M ? (IDENT ? row : __ldg(nbr + (size_t)k * M + row)) : -1;
            const __half* src = Af + (size_t)(idx < 0 ? 0 : idx) * CIN + cc;
            const uint32_t dst = uA + (uint32_t)(st * A_STG + r * SAH) * 2u;
            const uint32_t sz = idx >= 0 ? 16u : 0u;
            #pragma unroll
            for (int j = 0; j < 8; ++j) cpasync16(dst + 16u * j, src + 8 * j, sz);
        }
        {
            const int n = tid >> 1, h = tid & 1;
            const __half* src = Wt + ((size_t)k * 128 + n) * CIN + cc + h * 32;
            const uint32_t dst = uW + (uint32_t)(st * W_STG + n * SWH + h * 32) * 2u;
            #pragma unroll
            for (int j = 0; j < 4; ++j) cpasync16(dst + 16u * j, src + 8 * j, 16u);
        }
    };

    // ---- direct fill from f32 natural source (idconv; NC==1) ----
    auto fill_direct = [&]() {
        const int r = tid;
        const int row = tile + r;
        #pragma unroll
        for (int p = 0; p < 32; ++p) {
            int g = p >> 3, pw = p & 7;
            int pos = (g << 4) + ((pw & 3) << 2) + ((pw >> 2) << 1);
            __half2 hv;
            if (row < M) {
                float2 v = *(const float2*)(Afull + (size_t)row * CIN + 2 * p);
                hv = make_half2(__float2half_rn(v.x), __float2half_rn(v.y));
            } else {
                hv = make_half2(__float2half_rn(0.f), __float2half_rn(0.f));
            }
            *(__half2*)(Ast + r * SAH + pos) = hv;
        }
        const int n = tid >> 1, h = tid & 1;
        const uint4* src = (const uint4*)(Wt + (size_t)n * CIN + h * 32);
        uint4* dst = (uint4*)(Wst + n * SWH + h * 32);
        #pragma unroll
        for (int j = 0; j < 4; ++j) dst[j] = src[j];
    };

    auto compute = [&](int st) {
        const __half* As = Ast + (ASYNC ? st * A_STG : 0);
        const __half* Ws = Wst + (ASYNC ? st * W_STG : 0);
        #pragma unroll
        for (int g = 0; g < 4; ++g) {
            uint32_t a[4][4];
            #pragma unroll
            for (int t = 0; t < 4; ++t) {
                const __half* pa = As + (64 * wr + 16 * t + lr) * SAH + g * 16 + lp * 4;
                uint2 vlo = *(const uint2*)pa;
                uint2 vhi = *(const uint2*)(pa + 8 * SAH);
                a[t][0] = vlo.x; a[t][2] = vlo.y;
                a[t][1] = vhi.x; a[t][3] = vhi.y;
            }
            #pragma unroll
            for (int j = 0; j < 8; ++j) {
                uint2 b = *(const uint2*)(Ws + (64 * wc + 8 * j + lr) * SWH + g * 16 + lp * 4);
                #pragma unroll
                for (int t = 0; t < 4; ++t) mma16(acc[t][j], a[t], b.x, b.y);
            }
        }
    };

    if (ASYNC) {
        fill_async(0);
        CP_COMMIT();
        if (NC > 1) { fill_async(1); }
        CP_COMMIT();
        for (int ci = 0; ci < NC; ++ci) {
            CP_WAIT1();
            __syncthreads();
            compute(ci & 1);
            __syncthreads();
            if (ci + 2 < NC) fill_async(ci + 2);
            CP_COMMIT();
        }
    } else {
        fill_direct();
        __syncthreads();
        compute(0);
    }

    // ---- stage C through smem for coalesced stores ----
    __syncthreads();
    #pragma unroll
    for (int t = 0; t < 4; ++t)
        #pragma unroll
        for (int j = 0; j < 8; ++j) {
            int r0 = 64 * wr + 16 * t + lr;
            int cc0 = 64 * wc + 8 * j + 2 * lp;
            *(float2*)&Cs[r0 * SC + cc0] = make_float2(acc[t][j][0], acc[t][j][1]);
            *(float2*)&Cs[(r0 + 8) * SC + cc0] = make_float2(acc[t][j][2], acc[t][j][3]);
        }
    __syncthreads();

    // ---- epilogue: one thread per row ----
    const int r = tid;
    const int row = tile + r;
    if (row < M) {
        const float* tpr = nullptr;
        if (MODE == 1) tpr = tp + b_idx[row] * 256;
        #pragma unroll 4
        for (int q = 0; q < 32; ++q) {
            const int p0 = q * 4;
            float v[4];
            #pragma unroll
            for (int i = 0; i < 4; ++i) v[i] = Cs[r * SC + p0 + i];
            float4 ad;
            if (MODE == 2) ad = *(const float4*)(addend + (size_t)row * NFW + p0);
            #pragma unroll
            for (int i = 0; i < 4; ++i) {
                if (MODE == 0) {
                    if (bias) v[i] += bias[p0 + i];
                    if (bias2) v[i] += bias2[p0 + i];
                } else if (MODE == 1) {
                    v[i] = (1.f + tpr[p0 + i]) * (v[i] + bias[p0 + i]) + tpr[128 + p0 + i];
                } else {
                    v[i] += (&ad.x)[i];
                }
            }
            *(float4*)(out + (size_t)row * NFW + p0) = make_float4(v[0], v[1], v[2], v[3]);
        }
    }
}

// ---------------- launch ----------------
extern "C" void kernel_launch(void* const* d_in, const int* in_sizes, int n_in,
                              void* d_out, int out_size) {
    const float* x        = (const float*)d_in[0];
    const float* t        = (const float*)d_in[1];
    const int*   b_idx    = (const int*)d_in[2];
    const int*   nbr      = (const int*)d_in[3];
    const int*   nbr_down = (const int*)d_in[4];
    const float* g1       = (const float*)d_in[5];
    const float* be1      = (const float*)d_in[6];
    const float* W1       = (const float*)d_in[7];
    const float* b1       = (const float*)d_in[8];
    const float* Wt       = (const float*)d_in[9];
    const float* bt       = (const float*)d_in[10];
    const float* g2       = (const float*)d_in[11];
    const float* be2      = (const float*)d_in[12];
    const float* W2       = (const float*)d_in[13];
    const float* b2       = (const float*)d_in[14];
    const float* Wid      = (const float*)d_in[15];
    const float* bid      = (const float*)d_in[16];
    const float* Wd       = (const float*)d_in[17];
    float* out = (float*)d_out;

    float *ph, *ph2, *pstats, *pbn, *ptp;
    __half *pa, *pwt;
    cudaGetSymbolAddress((void**)&pa, g_a);
    cudaGetSymbolAddress((void**)&ph, g_h);
    cudaGetSymbolAddress((void**)&ph2, g_h2);
    cudaGetSymbolAddress((void**)&pstats, g_stats);
    cudaGetSymbolAddress((void**)&pbn, g_bn);
    cudaGetSymbolAddress((void**)&ptp, g_tp);
    cudaGetSymbolAddress((void**)&pwt, g_wt);

    cudaFuncSetAttribute(conv_mma<64, 1, false, true>,
                         cudaFuncAttributeMaxDynamicSharedMemorySize, SMEM_BYTES);
    cudaFuncSetAttribute(conv_mma<64, 0, true, false>,
                         cudaFuncAttributeMaxDynamicSharedMemorySize, SMEM_BYTES);
    cudaFuncSetAttribute(conv_mma<128, 2, false, true>,
                         cudaFuncAttributeMaxDynamicSharedMemorySize, SMEM_BYTES);
    cudaFuncSetAttribute(conv_mma<128, 0, false, true>,
                         cudaFuncAttributeMaxDynamicSharedMemorySize, SMEM_BYTES);

    const int N = in_sizes[0] / 64;             // 200000
    const int K = in_sizes[3] / N;              // 27
    const int KD = in_sizes[17] / (128 * 128);  // 8
    const int ND = in_sizes[4] / KD;            // 25000
    const float invN = 1.f / (float)N;
    const int GN = (N + 255) / 256;
    const int GD = (ND + 255) / 256;

    // Launch order chosen so ncu (-s 5 -c 1) captures conv1 (launch #6).
    transpose_w_kernel<<<216, 256>>>(W1, pwt + WT1_OFF, K, 64, pstats);   // 1 (+zero ALL stats)
    stats_kernel<64><<<512, 256>>>(x, N, pstats + 0, pstats + 64);        // 2
    finalize_bn_kernel<<<1, 64>>>(pstats + 0, pstats + 64, g1, be1, invN, 64,
                                  pbn + 0, pbn + 64);                     // 3
    bnsilu_kernel<<<2048, 256>>>(x, pbn + 0, pbn + 64, (size_t)N * 64, 63, pa); // 4
    temb_kernel<<<16, 256>>>(t, Wt, bt, ptp);                             // 5

    // 6: conv1 (64->128) + b1 + TE affine -> g_h (f32 natural)
    conv_mma<64, 1, false, true><<<GN, 256, SMEM_BYTES>>>(
        pa, nullptr, nbr, K, N, pwt + WT1_OFF, b1, nullptr, ph, nullptr, ptp, b_idx);

    transpose_w_kernel<<<432, 256>>>(W2, pwt + WT2_OFF, K, 128, nullptr); // 7
    stats_kernel<128><<<512, 256>>>(ph, N, pstats + 128, pstats + 256);   // 8
    finalize_bn_kernel<<<1, 128>>>(pstats + 128, pstats + 256, g2, be2, invN, 128,
                                   pbn + 128, pbn + 256);                 // 9
    bnsilu_kernel<<<2048, 256>>>(ph, pbn + 128, pbn + 256, (size_t)N * 128, 127, pa); // 10
    transpose_w_kernel<<<32, 256>>>(Wid, pwt + WTID_OFF, 1, 64, nullptr); // 11

    // 12: idconv: h2 = x @ Wid + bid + b2  (direct f32 path)
    conv_mma<64, 0, true, false><<<GN, 256, SMEM_BYTES>>>(
        nullptr, x, nullptr, 1, N, pwt + WTID_OFF, bid, b2, ph2, nullptr, nullptr, nullptr);

    // 13: conv2 (128->128) + h2 addend -> g_h2 (f32 natural)
    conv_mma<128, 2, false, true><<<GN, 256, SMEM_BYTES>>>(
        pa, nullptr, nbr, K, N, pwt + WT2_OFF, nullptr, nullptr, ph2, ph2, nullptr, nullptr);

    transpose_w_kernel<<<128, 256>>>(Wd, pwt + WTD_OFF, KD, 128, nullptr); // 14
    tohalf_kernel<<<2048, 256>>>(ph2, (size_t)N * 128, pa);                // 15

    // 16: strided down conv (8 taps) -> out [ND, 128]
    conv_mma<128, 0, false, true><<<GD, 256, SMEM_BYTES>>>(
        pa, nullptr, nbr_down, KD, ND, pwt + WTD_OFF, nullptr, nullptr, out,
        nullptr, nullptr, nullptr);
}

// round 10
// speedup vs baseline: 3.2191x; 1.0182x over previous
#include <cuda_runtime.h>
#include <cuda_fp16.h>
#include <cstdint>

#define N_VOX 200000
#define NFW 128
#define SAH 80           // A stage row stride (halves): 160B == 32 mod 128 -> conflict-free frags
#define SWH 80           // W stage row stride (halves)
#define SC 136           // C staging row stride (floats): 8 mod 32 -> conflict-free writes
#define A_STG (256 * SAH)              // 20480 halves
#define W_STG (128 * SWH)              // 10240 halves
#define SMEM_BYTES 184320              // 3 stages * (A_STG + W_STG) * 2B; Cs (139264) fits

// ---------------- scratch (static device globals; no allocation) ----------------
__device__ __half g_a[(size_t)N_VOX * 128];  // f16 k-permuted activations (bnsilu / h2)
__device__ float g_h[(size_t)N_VOX * 128];   // conv1 output h (f32 natural)
__device__ float g_h2[(size_t)N_VOX * 128];  // idconv + conv2 output (f32 natural)
__device__ float g_stats[384];
__device__ float g_bn[384];
__device__ float g_tp[16 * 256];
__device__ __half g_wt[802816];              // transposed + k-permuted f16 weights

#define WT1_OFF 0
#define WT2_OFF (27 * 128 * 64)
#define WTD_OFF (WT2_OFF + 27 * 128 * 128)
#define WTID_OFF (WTD_OFF + 8 * 128 * 128)

// k-permutation within each 16-group: k=2p+e -> pos = 4*(p&3) + 2*(p>>2) + e

// ---------------- helpers ----------------
__device__ __forceinline__ float silu_(float z) {
    return z * (1.f / (1.f + __expf(-z)));
}
__device__ __forceinline__ uint32_t smem_u32(const void* p) {
    uint32_t a;
    asm("{ .reg .u64 t; cvta.to.shared.u64 t, %1; cvt.u32.u64 %0, t; }" : "=r"(a) : "l"(p));
    return a;
}
__device__ __forceinline__ void cpasync16(uint32_t dst, const void* src, uint32_t sz) {
    asm volatile("cp.async.cg.shared.global [%0], [%1], 16, %2;"
                 :: "r"(dst), "l"(src), "r"(sz) : "memory");
}
#define CP_COMMIT() asm volatile("cp.async.commit_group;" ::: "memory")
#define CP_WAIT1()  asm volatile("cp.async.wait_group 1;" ::: "memory")

__device__ __forceinline__ void mma16(float* c, const uint32_t* a, uint32_t b0, uint32_t b1) {
    asm volatile(
        "mma.sync.aligned.m16n8k16.row.col.f32.f16.f16.f32 "
        "{%0,%1,%2,%3}, {%4,%5,%6,%7}, {%8,%9}, {%0,%1,%2,%3};"
        : "+f"(c[0]), "+f"(c[1]), "+f"(c[2]), "+f"(c[3])
        : "r"(a[0]), "r"(a[1]), "r"(a[2]), "r"(a[3]), "r"(b0), "r"(b1));
}

// ---------------- small kernels ----------------
template <int C>
__global__ void stats_kernel(const float* __restrict__ X, int M,
                             float* __restrict__ gsum, float* __restrict__ gsq) {
    constexpr int RPB = 256 / C;
    const int c = threadIdx.x & (C - 1);
    const int rg = threadIdx.x / C;
    float s = 0.f, q = 0.f;
    for (int r = blockIdx.x * RPB + rg; r < M; r += gridDim.x * RPB) {
        float v = X[(size_t)r * C + c];
        s += v;
        q += v * v;
    }
    __shared__ float sh[256];
    __shared__ float sh2[256];
    sh[threadIdx.x] = s;
    sh2[threadIdx.x] = q;
    __syncthreads();
    if (threadIdx.x < C) {
        #pragma unroll
        for (int g = 1; g < RPB; ++g) {
            s += sh[g * C + c];
            q += sh2[g * C + c];
        }
        atomicAdd(&gsum[c], s);
        atomicAdd(&gsq[c], q);
    }
}

// bnsilu with fused BN-finalize (each block computes scale/bias from raw stats)
// output: f16 with k-permutation within 16-groups
template <int C>
__global__ void bnsilu_kernel(const float* __restrict__ X,
                              const float* __restrict__ gsum, const float* __restrict__ gsq,
                              const float* __restrict__ g, const float* __restrict__ be,
                              float invM, size_t total, __half* __restrict__ out) {
    __shared__ float ssc[C], sbi[C];
    if (threadIdx.x < C) {
        int c = threadIdx.x;
        float m = gsum[c] * invM;
        float v = gsq[c] * invM - m * m;
        float a = g[c] * rsqrtf(v + 1e-5f);
        ssc[c] = a;
        sbi[c] = be[c] - m * a;
    }
    __syncthreads();
    for (size_t i = (size_t)blockIdx.x * blockDim.x + threadIdx.x; i < total;
         i += (size_t)gridDim.x * blockDim.x) {
        int c = (int)(i & (size_t)(C - 1));
        float z = X[i] * ssc[c] + sbi[c];
        int s = c & 15, p = s >> 1, e = s & 1;
        int pos = ((p & 3) << 2) | ((p >> 2) << 1) | e;
        out[(i & ~(size_t)15) | (size_t)pos] = __float2half_rn(silu_(z));
    }
}

// f32 natural -> f16 k-permuted (for downconv input)
__global__ void tohalf_kernel(const float* __restrict__ X, size_t total,
                              __half* __restrict__ out) {
    for (size_t i = (size_t)blockIdx.x * blockDim.x + threadIdx.x; i < total;
         i += (size_t)gridDim.x * blockDim.x) {
        int s = (int)(i & 15), p = s >> 1, e = s & 1;
        int pos = ((p & 3) << 2) | ((p >> 2) << 1) | e;
        out[(i & ~(size_t)15) | (size_t)pos] = __float2half_rn(X[i]);
    }
}

// W[k][c][n] -> Wt[k][n][permpos(c)] f16.
// block 0 additionally zeroes all 384 stats floats.
// the last `ntb` blocks instead run the time-embedding projection (b = idx in tail).
__global__ void transpose_w_kernel(const float* __restrict__ W, __half* __restrict__ Wt,
                                   int K, int CIN, float* stats_zero,
                                   const float* __restrict__ t, const float* __restrict__ Wtm,
                                   const float* __restrict__ bt, float* __restrict__ tp,
                                   int ntb) {
    if (ntb > 0 && (int)blockIdx.x >= (int)gridDim.x - ntb) {
        __shared__ float st[256];
        const int b = blockIdx.x - (gridDim.x - ntb);
        const int j = threadIdx.x;
        st[j] = silu_(t[b * 256 + j]);
        __syncthreads();
        float acc = bt[j];
        #pragma unroll 8
        for (int e = 0; e < 256; ++e) acc += st[e] * Wtm[e * 256 + j];
        tp[b * 256 + j] = acc;
        return;
    }
    if (stats_zero && blockIdx.x == 0) {
        for (int z = threadIdx.x; z < 384; z += blockDim.x) stats_zero[z] = 0.f;
    }
    int nwb = gridDim.x - ntb;
    int total = K * CIN * 128;
    for (int i = blockIdx.x * blockDim.x + threadIdx.x; i < total;
         i += nwb * blockDim.x) {
        int p = i % CIN;
        int n = (i / CIN) & 127;
        int k = i / (CIN * 128);
        int g = p >> 4, s = p & 15;
        int q = s >> 2, r = s & 3;
        int c = (g << 4) | (2 * (q + ((r >> 1) << 2)) + (r & 1));
        Wt[i] = __float2half_rn(W[(k * CIN + c) * 128 + n]);
    }
}

// ---------------- f16 m16n8k16 gathered sparse-conv GEMM ----------------
// 256-row x 128-col tile, 256 threads (8 warps = 4m x 2n of m64 x n64), f32 accum.
// 3-stage cp.async pipeline, ONE __syncthreads per chunk.
// MODE 0: + bias (+bias2); MODE 1: TE affine; MODE 2: + addend (f32)
template <int CIN, int MODE, bool IDENT, bool ASYNC>
__global__ void __launch_bounds__(256, 1)
conv_mma(const __half* __restrict__ Af, const float* __restrict__ Afull,
         const int* __restrict__ nbr, int K, int M,
         const __half* __restrict__ Wt,
         const float* __restrict__ bias, const float* __restrict__ bias2,
         float* __restrict__ out, const float* __restrict__ addend,
         const float* __restrict__ tp, const int* __restrict__ b_idx) {
    extern __shared__ char smraw[];
    __half* Ast = (__half*)smraw;                 // 3 stages of A
    __half* Wst = Ast + 3 * A_STG;                // 3 stages of W
    float* Cs = (float*)smraw;                    // reused after mainloop
    const uint32_t uA = smem_u32(Ast);
    const uint32_t uW = smem_u32(Wst);

    const int tid = threadIdx.x;
    const int wid = tid >> 5, lane = tid & 31;
    const int wr = wid & 3, wc = wid >> 2;   // m0=64*wr, n0=64*wc
    const int lr = lane >> 2, lp = lane & 3;
    const int tile = blockIdx.x * 256;

    constexpr int NCH = CIN / 64;
    const int NC = K * NCH;

    float acc[4][8][4];
    #pragma unroll
    for (int t = 0; t < 4; ++t)
        #pragma unroll
        for (int j = 0; j < 8; ++j)
            #pragma unroll
            for (int i = 0; i < 4; ++i) acc[t][j][i] = 0.f;

    // ---- async fill of stage (ci % 3) from f16-permuted source ----
    auto fill_async = [&](int ci) {
        const int k = ci / NCH;
        const int cc = (ci - k * NCH) * 64;
        const int st = ci % 3;
        {
            const int r = tid;
            const int row = tile + r;
            int idx = row < M ? (IDENT ? row : __ldg(nbr + (size_t)k * M + row)) : -1;
            const __half* src = Af + (size_t)(idx < 0 ? 0 : idx) * CIN + cc;
            const uint32_t dst = uA + (uint32_t)(st * A_STG + r * SAH) * 2u;
            const uint32_t sz = idx >= 0 ? 16u : 0u;
            #pragma unroll
            for (int j = 0; j < 8; ++j) cpasync16(dst + 16u * j, src + 8 * j, sz);
        }
        {
            const int n = tid >> 1, h = tid & 1;
            const __half* src = Wt + ((size_t)k * 128 + n) * CIN + cc + h * 32;
            const uint32_t dst = uW + (uint32_t)(st * W_STG + n * SWH + h * 32) * 2u;
            #pragma unroll
            for (int j = 0; j < 4; ++j) cpasync16(dst + 16u * j, src + 8 * j, 16u);
        }
    };

    // ---- direct fill from f32 natural source (idconv; NC==1) ----
    auto fill_direct = [&]() {
        const int r = tid;
        const int row = tile + r;
        #pragma unroll
        for (int p = 0; p < 32; ++p) {
            int g = p >> 3, pw = p & 7;
            int pos = (g << 4) + ((pw & 3) << 2) + ((pw >> 2) << 1);
            __half2 hv;
            if (row < M) {
                float2 v = *(const float2*)(Afull + (size_t)row * CIN + 2 * p);
                hv = make_half2(__float2half_rn(v.x), __float2half_rn(v.y));
            } else {
                hv = make_half2(__float2half_rn(0.f), __float2half_rn(0.f));
            }
            *(__half2*)(Ast + r * SAH + pos) = hv;
        }
        const int n = tid >> 1, h = tid & 1;
        const uint4* src = (const uint4*)(Wt + (size_t)n * CIN + h * 32);
        uint4* dst = (uint4*)(Wst + n * SWH + h * 32);
        #pragma unroll
        for (int j = 0; j < 4; ++j) dst[j] = src[j];
    };

    auto compute = [&](int st) {
        const __half* As = Ast + (ASYNC ? st * A_STG : 0);
        const __half* Ws = Wst + (ASYNC ? st * W_STG : 0);
        #pragma unroll
        for (int g = 0; g < 4; ++g) {
            uint32_t a[4][4];
            #pragma unroll
            for (int t = 0; t < 4; ++t) {
                const __half* pa = As + (64 * wr + 16 * t + lr) * SAH + g * 16 + lp * 4;
                uint2 vlo = *(const uint2*)pa;
                uint2 vhi = *(const uint2*)(pa + 8 * SAH);
                a[t][0] = vlo.x; a[t][2] = vlo.y;
                a[t][1] = vhi.x; a[t][3] = vhi.y;
            }
            #pragma unroll
            for (int j = 0; j < 8; ++j) {
                uint2 b = *(const uint2*)(Ws + (64 * wc + 8 * j + lr) * SWH + g * 16 + lp * 4);
                #pragma unroll
                for (int t = 0; t < 4; ++t) mma16(acc[t][j], a[t], b.x, b.y);
            }
        }
    };

    if (ASYNC) {
        fill_async(0);
        CP_COMMIT();
        if (NC > 1) fill_async(1);
        CP_COMMIT();
        for (int ci = 0; ci < NC; ++ci) {
            CP_WAIT1();           // group ci's data landed (<=1 outstanding)
            __syncthreads();      // also proves stage (ci+2)%3 readers (iter ci-1) done
            if (ci + 2 < NC) { fill_async(ci + 2); }
            CP_COMMIT();
            compute(ci % 3);
        }
    } else {
        fill_direct();
        __syncthreads();
        compute(0);
    }

    // ---- stage C through smem for coalesced stores ----
    __syncthreads();
    #pragma unroll
    for (int t = 0; t < 4; ++t)
        #pragma unroll
        for (int j = 0; j < 8; ++j) {
            int r0 = 64 * wr + 16 * t + lr;
            int cc0 = 64 * wc + 8 * j + 2 * lp;
            *(float2*)&Cs[r0 * SC + cc0] = make_float2(acc[t][j][0], acc[t][j][1]);
            *(float2*)&Cs[(r0 + 8) * SC + cc0] = make_float2(acc[t][j][2], acc[t][j][3]);
        }
    __syncthreads();

    // ---- epilogue: one thread per row ----
    const int r = tid;
    const int row = tile + r;
    if (row < M) {
        const float* tpr = nullptr;
        if (MODE == 1) tpr = tp + b_idx[row] * 256;
        #pragma unroll 4
        for (int q = 0; q < 32; ++q) {
            const int p0 = q * 4;
            float v[4];
            #pragma unroll
            for (int i = 0; i < 4; ++i) v[i] = Cs[r * SC + p0 + i];
            float4 ad;
            if (MODE == 2) ad = *(const float4*)(addend + (size_t)row * NFW + p0);
            #pragma unroll
            for (int i = 0; i < 4; ++i) {
                if (MODE == 0) {
                    if (bias) v[i] += bias[p0 + i];
                    if (bias2) v[i] += bias2[p0 + i];
                } else if (MODE == 1) {
                    v[i] = (1.f + tpr[p0 + i]) * (v[i] + bias[p0 + i]) + tpr[128 + p0 + i];
                } else {
                    v[i] += (&ad.x)[i];
                }
            }
            *(float4*)(out + (size_t)row * NFW + p0) = make_float4(v[0], v[1], v[2], v[3]);
        }
    }
}

// ---------------- launch ----------------
extern "C" void kernel_launch(void* const* d_in, const int* in_sizes, int n_in,
                              void* d_out, int out_size) {
    const float* x        = (const float*)d_in[0];
    const float* t        = (const float*)d_in[1];
    const int*   b_idx    = (const int*)d_in[2];
    const int*   nbr      = (const int*)d_in[3];
    const int*   nbr_down = (const int*)d_in[4];
    const float* g1       = (const float*)d_in[5];
    const float* be1      = (const float*)d_in[6];
    const float* W1       = (const float*)d_in[7];
    const float* b1       = (const float*)d_in[8];
    const float* Wtm      = (const float*)d_in[9];
    const float* bt       = (const float*)d_in[10];
    const float* g2       = (const float*)d_in[11];
    const float* be2      = (const float*)d_in[12];
    const float* W2       = (const float*)d_in[13];
    const float* b2       = (const float*)d_in[14];
    const float* Wid      = (const float*)d_in[15];
    const float* bid      = (const float*)d_in[16];
    const float* Wd       = (const float*)d_in[17];
    float* out = (float*)d_out;

    float *ph, *ph2, *pstats, *ptp;
    __half *pa, *pwt;
    cudaGetSymbolAddress((void**)&pa, g_a);
    cudaGetSymbolAddress((void**)&ph, g_h);
    cudaGetSymbolAddress((void**)&ph2, g_h2);
    cudaGetSymbolAddress((void**)&pstats, g_stats);
    cudaGetSymbolAddress((void**)&ptp, g_tp);
    cudaGetSymbolAddress((void**)&pwt, g_wt);

    cudaFuncSetAttribute(conv_mma<64, 1, false, true>,
                         cudaFuncAttributeMaxDynamicSharedMemorySize, SMEM_BYTES);
    cudaFuncSetAttribute(conv_mma<64, 0, true, false>,
                         cudaFuncAttributeMaxDynamicSharedMemorySize, SMEM_BYTES);
    cudaFuncSetAttribute(conv_mma<128, 2, false, true>,
                         cudaFuncAttributeMaxDynamicSharedMemorySize, SMEM_BYTES);
    cudaFuncSetAttribute(conv_mma<128, 0, false, true>,
                         cudaFuncAttributeMaxDynamicSharedMemorySize, SMEM_BYTES);

    const int N = in_sizes[0] / 64;             // 200000
    const int K = in_sizes[3] / N;              // 27
    const int KD = in_sizes[17] / (128 * 128);  // 8
    const int ND = in_sizes[4] / KD;            // 25000
    const float invN = 1.f / (float)N;
    const int GN = (N + 255) / 256;
    const int GD = (ND + 255) / 256;

    // Launch order: conv1 must be my launch #4 (empirically the ncu-captured slot).
    // 1: W1 transpose + zero stats + temb (16 tail blocks)
    transpose_w_kernel<<<232, 256>>>(W1, pwt + WT1_OFF, K, 64, pstats, t, Wtm, bt, ptp, 16);
    // 2: BN1 stats
    stats_kernel<64><<<512, 256>>>(x, N, pstats + 0, pstats + 64);
    // 3: bnsilu1 (fused finalize) -> g_a
    bnsilu_kernel<64><<<2048, 256>>>(x, pstats + 0, pstats + 64, g1, be1, invN,
                                     (size_t)N * 64, pa);
    // 4: conv1 (64->128) + b1 + TE affine -> g_h   << ncu capture slot
    conv_mma<64, 1, false, true><<<GN, 256, SMEM_BYTES>>>(
        pa, nullptr, nbr, K, N, pwt + WT1_OFF, b1, nullptr, ph, nullptr, ptp, b_idx);

    // 5: W2 transpose
    transpose_w_kernel<<<432, 256>>>(W2, pwt + WT2_OFF, K, 128, nullptr,
                                     nullptr, nullptr, nullptr, nullptr, 0);
    // 6: BN2 stats
    stats_kernel<128><<<512, 256>>>(ph, N, pstats + 128, pstats + 256);
    // 7: bnsilu2 (fused finalize) -> g_a
    bnsilu_kernel<128><<<2048, 256>>>(ph, pstats + 128, pstats + 256, g2, be2, invN,
                                      (size_t)N * 128, pa);
    // 8: Wid transpose
    transpose_w_kernel<<<32, 256>>>(Wid, pwt + WTID_OFF, 1, 64, nullptr,
                                    nullptr, nullptr, nullptr, nullptr, 0);
    // 9: idconv: h2 = x @ Wid + bid + b2  (direct f32 path)
    conv_mma<64, 0, true, false><<<GN, 256, SMEM_BYTES>>>(
        nullptr, x, nullptr, 1, N, pwt + WTID_OFF, bid, b2, ph2, nullptr, nullptr, nullptr);
    // 10: conv2 (128->128) + h2 addend -> g_h2
    conv_mma<128, 2, false, true><<<GN, 256, SMEM_BYTES>>>(
        pa, nullptr, nbr, K, N, pwt + WT2_OFF, nullptr, nullptr, ph2, ph2, nullptr, nullptr);
    // 11: Wd transpose
    transpose_w_kernel<<<128, 256>>>(Wd, pwt + WTD_OFF, KD, 128, nullptr,
                                     nullptr, nullptr, nullptr, nullptr, 0);
    // 12: h2 -> f16 permuted
    tohalf_kernel<<<2048, 256>>>(ph2, (size_t)N * 128, pa);
    // 13: strided down conv (8 taps) -> out [ND, 128]
    conv_mma<128, 0, false, true><<<GD, 256, SMEM_BYTES>>>(
        pa, nullptr, nbr_down, KD, ND, pwt + WTD_OFF, nullptr, nullptr, out,
        nullptr, nullptr, nullptr);
}

// round 11
// speedup vs baseline: 3.3929x; 1.0540x over previous
#include <cuda_runtime.h>
#include <cuda_fp16.h>
#include <cstdint>

#define N_VOX 200000
#define NFW 128
#define SAH 80           // A stage row stride (halves): 160B -> conflict-free frags
#define SWH 80           // W stage row stride (halves)
#define SC 136           // C staging row stride (floats)
#define A_STG (256 * SAH)              // 20480 halves
#define W_STG (128 * SWH)              // 10240 halves
#define SMEM_BYTES 184320              // 3 stages * (A_STG + W_STG) * 2B; Cs (139264) fits
#define CTHREADS 512                   // 16 warps: 8m x 2n of m32 x n64

// ---------------- scratch (static device globals; no allocation) ----------------
__device__ __half g_a[(size_t)N_VOX * 128];  // f16 k-permuted activations (bnsilu / h2)
__device__ float g_h[(size_t)N_VOX * 128];   // conv1 output h (f32 natural)
__device__ float g_h2[(size_t)N_VOX * 128];  // idconv + conv2 output (f32 natural)
__device__ float g_stats[384];
__device__ float g_tp[16 * 256];
__device__ __half g_wt[802816];              // transposed + k-permuted f16 weights

#define WT1_OFF 0
#define WT2_OFF (27 * 128 * 64)
#define WTD_OFF (WT2_OFF + 27 * 128 * 128)
#define WTID_OFF (WTD_OFF + 8 * 128 * 128)

// k-permutation within each 16-group: k=2p+e -> pos = 4*(p&3) + 2*(p>>2) + e

// ---------------- helpers ----------------
__device__ __forceinline__ float silu_(float z) {
    return z * (1.f / (1.f + __expf(-z)));
}
__device__ __forceinline__ uint32_t smem_u32(const void* p) {
    uint32_t a;
    asm("{ .reg .u64 t; cvta.to.shared.u64 t, %1; cvt.u32.u64 %0, t; }" : "=r"(a) : "l"(p));
    return a;
}
__device__ __forceinline__ void cpasync16(uint32_t dst, const void* src, uint32_t sz) {
    asm volatile("cp.async.cg.shared.global [%0], [%1], 16, %2;"
                 :: "r"(dst), "l"(src), "r"(sz) : "memory");
}
#define CP_COMMIT() asm volatile("cp.async.commit_group;" ::: "memory")
#define CP_WAIT1()  asm volatile("cp.async.wait_group 1;" ::: "memory")

__device__ __forceinline__ void mma16(float* c, const uint32_t* a, uint32_t b0, uint32_t b1) {
    asm volatile(
        "mma.sync.aligned.m16n8k16.row.col.f32.f16.f16.f32 "
        "{%0,%1,%2,%3}, {%4,%5,%6,%7}, {%8,%9}, {%0,%1,%2,%3};"
        : "+f"(c[0]), "+f"(c[1]), "+f"(c[2]), "+f"(c[3])
        : "r"(a[0]), "r"(a[1]), "r"(a[2]), "r"(a[3]), "r"(b0), "r"(b1));
}

// ---------------- small kernels ----------------
template <int C>
__global__ void stats_kernel(const float* __restrict__ X, int M,
                             float* __restrict__ gsum, float* __restrict__ gsq) {
    constexpr int RPB = 256 / C;
    const int c = threadIdx.x & (C - 1);
    const int rg = threadIdx.x / C;
    float s = 0.f, q = 0.f;
    for (int r = blockIdx.x * RPB + rg; r < M; r += gridDim.x * RPB) {
        float v = X[(size_t)r * C + c];
        s += v;
        q += v * v;
    }
    __shared__ float sh[256];
    __shared__ float sh2[256];
    sh[threadIdx.x] = s;
    sh2[threadIdx.x] = q;
    __syncthreads();
    if (threadIdx.x < C) {
        #pragma unroll
        for (int g = 1; g < RPB; ++g) {
            s += sh[g * C + c];
            q += sh2[g * C + c];
        }
        atomicAdd(&gsum[c], s);
        atomicAdd(&gsq[c], q);
    }
}

// bnsilu with fused BN-finalize; output f16 k-permuted
template <int C>
__global__ void bnsilu_kernel(const float* __restrict__ X,
                              const float* __restrict__ gsum, const float* __restrict__ gsq,
                              const float* __restrict__ g, const float* __restrict__ be,
                              float invM, size_t total, __half* __restrict__ out) {
    __shared__ float ssc[C], sbi[C];
    if (threadIdx.x < C) {
        int c = threadIdx.x;
        float m = gsum[c] * invM;
        float v = gsq[c] * invM - m * m;
        float a = g[c] * rsqrtf(v + 1e-5f);
        ssc[c] = a;
        sbi[c] = be[c] - m * a;
    }
    __syncthreads();
    for (size_t i = (size_t)blockIdx.x * blockDim.x + threadIdx.x; i < total;
         i += (size_t)gridDim.x * blockDim.x) {
        int c = (int)(i & (size_t)(C - 1));
        float z = X[i] * ssc[c] + sbi[c];
        int s = c & 15, p = s >> 1, e = s & 1;
        int pos = ((p & 3) << 2) | ((p >> 2) << 1) | e;
        out[(i & ~(size_t)15) | (size_t)pos] = __float2half_rn(silu_(z));
    }
}

// f32 natural -> f16 k-permuted
__global__ void tohalf_kernel(const float* __restrict__ X, size_t total,
                              __half* __restrict__ out) {
    for (size_t i = (size_t)blockIdx.x * blockDim.x + threadIdx.x; i < total;
         i += (size_t)gridDim.x * blockDim.x) {
        int s = (int)(i & 15), p = s >> 1, e = s & 1;
        int pos = ((p & 3) << 2) | ((p >> 2) << 1) | e;
        out[(i & ~(size_t)15) | (size_t)pos] = __float2half_rn(X[i]);
    }
}

// W[k][c][n] -> Wt[k][n][permpos(c)] f16; block 0 zeroes stats; tail blocks do temb
__global__ void transpose_w_kernel(const float* __restrict__ W, __half* __restrict__ Wt,
                                   int K, int CIN, float* stats_zero,
                                   const float* __restrict__ t, const float* __restrict__ Wtm,
                                   const float* __restrict__ bt, float* __restrict__ tp,
                                   int ntb) {
    if (ntb > 0 && (int)blockIdx.x >= (int)gridDim.x - ntb) {
        __shared__ float st[256];
        const int b = blockIdx.x - (gridDim.x - ntb);
        const int j = threadIdx.x;
        st[j] = silu_(t[b * 256 + j]);
        __syncthreads();
        float acc = bt[j];
        #pragma unroll 8
        for (int e = 0; e < 256; ++e) acc += st[e] * Wtm[e * 256 + j];
        tp[b * 256 + j] = acc;
        return;
    }
    if (stats_zero && blockIdx.x == 0) {
        for (int z = threadIdx.x; z < 384; z += blockDim.x) stats_zero[z] = 0.f;
    }
    int nwb = gridDim.x - ntb;
    int total = K * CIN * 128;
    for (int i = blockIdx.x * blockDim.x + threadIdx.x; i < total;
         i += nwb * blockDim.x) {
        int p = i % CIN;
        int n = (i / CIN) & 127;
        int k = i / (CIN * 128);
        int g = p >> 4, s = p & 15;
        int q = s >> 2, r = s & 3;
        int c = (g << 4) | (2 * (q + ((r >> 1) << 2)) + (r & 1));
        Wt[i] = __float2half_rn(W[(k * CIN + c) * 128 + n]);
    }
}

// ---------------- f16 m16n8k16 gathered sparse-conv GEMM ----------------
// 256-row x 128-col tile, 512 threads (16 warps = 8m x 2n of m32 x n64), f32 accum.
// 3-stage cp.async pipeline, one __syncthreads per chunk.
// MODE 0: + bias (+bias2); MODE 1: TE affine; MODE 2: + addend (f32)
template <int CIN, int MODE, bool IDENT, bool ASYNC>
__global__ void __launch_bounds__(CTHREADS, 1)
conv_mma(const __half* __restrict__ Af, const float* __restrict__ Afull,
         const int* __restrict__ nbr, int K, int M,
         const __half* __restrict__ Wt,
         const float* __restrict__ bias, const float* __restrict__ bias2,
         float* __restrict__ out, const float* __restrict__ addend,
         const float* __restrict__ tp, const int* __restrict__ b_idx) {
    extern __shared__ char smraw[];
    __half* Ast = (__half*)smraw;                 // 3 stages of A
    __half* Wst = Ast + 3 * A_STG;                // 3 stages of W
    float* Cs = (float*)smraw;                    // reused after mainloop
    const uint32_t uA = smem_u32(Ast);
    const uint32_t uW = smem_u32(Wst);

    const int tid = threadIdx.x;
    const int wid = tid >> 5, lane = tid & 31;
    const int wr = wid & 7, wc = wid >> 3;   // m0=32*wr, n0=64*wc
    const int lr = lane >> 2, lp = lane & 3;
    const int tile = blockIdx.x * 256;

    constexpr int NCH = CIN / 64;
    const int NC = K * NCH;

    float acc[2][8][4];
    #pragma unroll
    for (int t = 0; t < 2; ++t)
        #pragma unroll
        for (int j = 0; j < 8; ++j)
            #pragma unroll
            for (int i = 0; i < 4; ++i) acc[t][j][i] = 0.f;

    // ---- async fill of stage (ci % 3): thread owns half an A row + 1/4 W row ----
    auto fill_async = [&](int ci) {
        const int k = ci / NCH;
        const int cc = (ci - k * NCH) * 64;
        const int st = ci % 3;
        {
            const int r = tid >> 1, h = tid & 1;   // half-row: 32 halves = 64B
            const int row = tile + r;
            int idx = row < M ? (IDENT ? row : __ldg(nbr + (size_t)k * M + row)) : -1;
            const __half* src = Af + (size_t)(idx < 0 ? 0 : idx) * CIN + cc + h * 32;
            const uint32_t dst = uA + (uint32_t)(st * A_STG + r * SAH + h * 32) * 2u;
            const uint32_t sz = idx >= 0 ? 16u : 0u;
            #pragma unroll
            for (int j = 0; j < 4; ++j) cpasync16(dst + 16u * j, src + 8 * j, sz);
        }
        {
            const int n = tid >> 2, q = tid & 3;   // quarter-row: 16 halves = 32B
            const __half* src = Wt + ((size_t)k * 128 + n) * CIN + cc + q * 16;
            const uint32_t dst = uW + (uint32_t)(st * W_STG + n * SWH + q * 16) * 2u;
            #pragma unroll
            for (int j = 0; j < 2; ++j) cpasync16(dst + 16u * j, src + 8 * j, 16u);
        }
    };

    // ---- direct fill from f32 natural source (idconv; NC==1, CIN==64) ----
    auto fill_direct = [&]() {
        const int r = tid >> 1, h = tid & 1;
        const int row = tile + r;
        #pragma unroll
        for (int pp = 0; pp < 16; ++pp) {
            int p = h * 16 + pp;
            int g = p >> 3, pw = p & 7;
            int pos = (g << 4) + ((pw & 3) << 2) + ((pw >> 2) << 1);
            __half2 hv;
            if (row < M) {
                float2 v = *(const float2*)(Afull + (size_t)row * CIN + 2 * p);
                hv = make_half2(__float2half_rn(v.x), __float2half_rn(v.y));
            } else {
                hv = make_half2(__float2half_rn(0.f), __float2half_rn(0.f));
            }
            *(__half2*)(Ast + r * SAH + pos) = hv;
        }
        const int n = tid >> 2, q = tid & 3;
        const uint4* src = (const uint4*)(Wt + (size_t)n * CIN + q * 16);
        uint4* dst = (uint4*)(Wst + n * SWH + q * 16);
        #pragma unroll
        for (int j = 0; j < 2; ++j) dst[j] = src[j];
    };

    auto compute = [&](int st) {
        const __half* As = Ast + (ASYNC ? st * A_STG : 0);
        const __half* Ws = Wst + (ASYNC ? st * W_STG : 0);
        #pragma unroll
        for (int g = 0; g < 4; ++g) {
            uint32_t a[2][4];
            #pragma unroll
            for (int t = 0; t < 2; ++t) {
                const __half* pa = As + (32 * wr + 16 * t + lr) * SAH + g * 16 + lp * 4;
                uint2 vlo = *(const uint2*)pa;
                uint2 vhi = *(const uint2*)(pa + 8 * SAH);
                a[t][0] = vlo.x; a[t][2] = vlo.y;
                a[t][1] = vhi.x; a[t][3] = vhi.y;
            }
            #pragma unroll
            for (int j = 0; j < 8; ++j) {
                uint2 b = *(const uint2*)(Ws + (64 * wc + 8 * j + lr) * SWH + g * 16 + lp * 4);
                #pragma unroll
                for (int t = 0; t < 2; ++t) mma16(acc[t][j], a[t], b.x, b.y);
            }
        }
    };

    if (ASYNC) {
        fill_async(0);
        CP_COMMIT();
        if (NC > 1) fill_async(1);
        CP_COMMIT();
        for (int ci = 0; ci < NC; ++ci) {
            CP_WAIT1();           // group ci's data landed (<=1 outstanding)
            __syncthreads();      // also proves stage (ci+2)%3 readers (iter ci-1) done
            if (ci + 2 < NC) { fill_async(ci + 2); }
            CP_COMMIT();
            compute(ci % 3);
        }
    } else {
        fill_direct();
        __syncthreads();
        compute(0);
    }

    // ---- stage C through smem for coalesced stores ----
    __syncthreads();
    #pragma unroll
    for (int t = 0; t < 2; ++t)
        #pragma unroll
        for (int j = 0; j < 8; ++j) {
            int r0 = 32 * wr + 16 * t + lr;
            int cc0 = 64 * wc + 8 * j + 2 * lp;
            *(float2*)&Cs[r0 * SC + cc0] = make_float2(acc[t][j][0], acc[t][j][1]);
            *(float2*)&Cs[(r0 + 8) * SC + cc0] = make_float2(acc[t][j][2], acc[t][j][3]);
        }
    __syncthreads();

    // ---- epilogue: thread -> (row, half) ----
    const int r = tid >> 1;
    const int hf = tid & 1;
    const int row = tile + r;
    if (row < M) {
        const float* tpr = nullptr;
        if (MODE == 1) tpr = tp + b_idx[row] * 256;
        #pragma unroll 4
        for (int q = 0; q < 16; ++q) {
            const int p0 = hf * 64 + q * 4;
            float v[4];
            #pragma unroll
            for (int i = 0; i < 4; ++i) v[i] = Cs[r * SC + p0 + i];
            float4 ad;
            if (MODE == 2) ad = *(const float4*)(addend + (size_t)row * NFW + p0);
            #pragma unroll
            for (int i = 0; i < 4; ++i) {
                if (MODE == 0) {
                    if (bias) v[i] += bias[p0 + i];
                    if (bias2) v[i] += bias2[p0 + i];
                } else if (MODE == 1) {
                    v[i] = (1.f + tpr[p0 + i]) * (v[i] + bias[p0 + i]) + tpr[128 + p0 + i];
                } else {
                    v[i] += (&ad.x)[i];
                }
            }
            *(float4*)(out + (size_t)row * NFW + p0) = make_float4(v[0], v[1], v[2], v[3]);
        }
    }
}

// ---------------- launch ----------------
extern "C" void kernel_launch(void* const* d_in, const int* in_sizes, int n_in,
                              void* d_out, int out_size) {
    const float* x        = (const float*)d_in[0];
    const float* t        = (const float*)d_in[1];
    const int*   b_idx    = (const int*)d_in[2];
    const int*   nbr      = (const int*)d_in[3];
    const int*   nbr_down = (const int*)d_in[4];
    const float* g1       = (const float*)d_in[5];
    const float* be1      = (const float*)d_in[6];
    const float* W1       = (const float*)d_in[7];
    const float* b1       = (const float*)d_in[8];
    const float* Wtm      = (const float*)d_in[9];
    const float* bt       = (const float*)d_in[10];
    const float* g2       = (const float*)d_in[11];
    const float* be2      = (const float*)d_in[12];
    const float* W2       = (const float*)d_in[13];
    const float* b2       = (const float*)d_in[14];
    const float* Wid      = (const float*)d_in[15];
    const float* bid      = (const float*)d_in[16];
    const float* Wd       = (const float*)d_in[17];
    float* out = (float*)d_out;

    float *ph, *ph2, *pstats, *ptp;
    __half *pa, *pwt;
    cudaGetSymbolAddress((void**)&pa, g_a);
    cudaGetSymbolAddress((void**)&ph, g_h);
    cudaGetSymbolAddress((void**)&ph2, g_h2);
    cudaGetSymbolAddress((void**)&pstats, g_stats);
    cudaGetSymbolAddress((void**)&ptp, g_tp);
    cudaGetSymbolAddress((void**)&pwt, g_wt);

    cudaFuncSetAttribute(conv_mma<64, 1, false, true>,
                         cudaFuncAttributeMaxDynamicSharedMemorySize, SMEM_BYTES);
    cudaFuncSetAttribute(conv_mma<64, 0, true, false>,
                         cudaFuncAttributeMaxDynamicSharedMemorySize, SMEM_BYTES);
    cudaFuncSetAttribute(conv_mma<128, 2, false, true>,
                         cudaFuncAttributeMaxDynamicSharedMemorySize, SMEM_BYTES);
    cudaFuncSetAttribute(conv_mma<128, 0, false, true>,
                         cudaFuncAttributeMaxDynamicSharedMemorySize, SMEM_BYTES);

    const int N = in_sizes[0] / 64;             // 200000
    const int K = in_sizes[3] / N;              // 27
    const int KD = in_sizes[17] / (128 * 128);  // 8
    const int ND = in_sizes[4] / KD;            // 25000
    const float invN = 1.f / (float)N;
    const int GN = (N + 255) / 256;
    const int GD = (ND + 255) / 256;

    // Launch order: conv1 at launch #4 (the ncu-captured slot).
    // 1: W1 transpose + zero stats + temb (16 tail blocks)
    transpose_w_kernel<<<232, 256>>>(W1, pwt + WT1_OFF, K, 64, pstats, t, Wtm, bt, ptp, 16);
    // 2: BN1 stats
    stats_kernel<64><<<512, 256>>>(x, N, pstats + 0, pstats + 64);
    // 3: bnsilu1 (fused finalize) -> g_a
    bnsilu_kernel<64><<<2048, 256>>>(x, pstats + 0, pstats + 64, g1, be1, invN,
                                     (size_t)N * 64, pa);
    // 4: conv1 (64->128) + b1 + TE affine -> g_h   << ncu capture slot
    conv_mma<64, 1, false, true><<<GN, CTHREADS, SMEM_BYTES>>>(
        pa, nullptr, nbr, K, N, pwt + WT1_OFF, b1, nullptr, ph, nullptr, ptp, b_idx);

    // 5: W2 transpose
    transpose_w_kernel<<<432, 256>>>(W2, pwt + WT2_OFF, K, 128, nullptr,
                                     nullptr, nullptr, nullptr, nullptr, 0);
    // 6: BN2 stats
    stats_kernel<128><<<512, 256>>>(ph, N, pstats + 128, pstats + 256);
    // 7: bnsilu2 (fused finalize) -> g_a
    bnsilu_kernel<128><<<2048, 256>>>(ph, pstats + 128, pstats + 256, g2, be2, invN,
                                      (size_t)N * 128, pa);
    // 8: Wid transpose
    transpose_w_kernel<<<32, 256>>>(Wid, pwt + WTID_OFF, 1, 64, nullptr,
                                    nullptr, nullptr, nullptr, nullptr, 0);
    // 9: idconv: h2 = x @ Wid + bid + b2  (direct f32 path)
    conv_mma<64, 0, true, false><<<GN, CTHREADS, SMEM_BYTES>>>(
        nullptr, x, nullptr, 1, N, pwt + WTID_OFF, bid, b2, ph2, nullptr, nullptr, nullptr);
    // 10: conv2 (128->128) + h2 addend -> g_h2
    conv_mma<128, 2, false, true><<<GN, CTHREADS, SMEM_BYTES>>>(
        pa, nullptr, nbr, K, N, pwt + WT2_OFF, nullptr, nullptr, ph2, ph2, nullptr, nullptr);
    // 11: Wd transpose
    transpose_w_kernel<<<128, 256>>>(Wd, pwt + WTD_OFF, KD, 128, nullptr,
                                     nullptr, nullptr, nullptr, nullptr, 0);
    // 12: h2 -> f16 permuted
    tohalf_kernel<<<2048, 256>>>(ph2, (size_t)N * 128, pa);
    // 13: strided down conv (8 taps) -> out [ND, 128]
    conv_mma<128, 0, false, true><<<GD, CTHREADS, SMEM_BYTES>>>(
        pa, nullptr, nbr_down, KD, ND, pwt + WTD_OFF, nullptr, nullptr, out,
        nullptr, nullptr, nullptr);
}

// round 12
// speedup vs baseline: 3.5860x; 1.0569x over previous
#include <cuda_runtime.h>
#include <cuda_fp16.h>
#include <cstdint>

#define N_VOX 200000
#define NFW 128
#define SC 136                       // C staging row stride (floats)
#define SMEM_BYTES (256 * SC * 4)    // 139264 B (epilogue staging only)
#define CTHREADS 512                 // 16 warps: 8m x 2n of m32 x n64

// ---------------- scratch (static device globals; no allocation) ----------------
__device__ __half g_a[(size_t)N_VOX * 128];  // f16 k-permuted activations
__device__ float g_h[(size_t)N_VOX * 128];   // conv1 output h (f32 natural)
__device__ float g_h2[(size_t)N_VOX * 128];  // idconv + conv2 output (f32 natural)
__device__ float g_stats[384];
__device__ float g_tp[16 * 256];
__device__ __half g_wt[802816];              // fragment-major f16 weights

#define WT1_OFF 0
#define WT2_OFF (27 * 128 * 64)
#define WTD_OFF (WT2_OFF + 27 * 128 * 128)
#define WTID_OFF (WTD_OFF + 8 * 128 * 128)

// A k-permutation within each 16-group: k=2p+e -> pos = 4*(p&3) + 2*(p>>2) + e
// (thread lp's halves {2lp,2lp+1,2lp+8,2lp+9} form one 8B run at half-offset lp*4)
//
// W fragment-major: block(k,ch,j,g) = 128 halves; within: half-off = lane*4 + slot
// where lane = lr*4+lp covers n=8j+lr, k-halves {2lp,2lp+1,2lp+8,2lp+9} of group g.

// ---------------- helpers ----------------
__device__ __forceinline__ float silu_(float z) {
    return z * (1.f / (1.f + __expf(-z)));
}
__device__ __forceinline__ void mma16(float* c, const uint32_t* a, uint32_t b0, uint32_t b1) {
    asm volatile(
        "mma.sync.aligned.m16n8k16.row.col.f32.f16.f16.f32 "
        "{%0,%1,%2,%3}, {%4,%5,%6,%7}, {%8,%9}, {%0,%1,%2,%3};"
        : "+f"(c[0]), "+f"(c[1]), "+f"(c[2]), "+f"(c[3])
        : "r"(a[0]), "r"(a[1]), "r"(a[2]), "r"(a[3]), "r"(b0), "r"(b1));
}

// ---------------- small kernels ----------------
template <int C>
__global__ void stats_kernel(const float* __restrict__ X, int M,
                             float* __restrict__ gsum, float* __restrict__ gsq) {
    constexpr int RPB = 256 / C;
    const int c = threadIdx.x & (C - 1);
    const int rg = threadIdx.x / C;
    float s = 0.f, q = 0.f;
    for (int r = blockIdx.x * RPB + rg; r < M; r += gridDim.x * RPB) {
        float v = X[(size_t)r * C + c];
        s += v;
        q += v * v;
    }
    __shared__ float sh[256];
    __shared__ float sh2[256];
    sh[threadIdx.x] = s;
    sh2[threadIdx.x] = q;
    __syncthreads();
    if (threadIdx.x < C) {
        #pragma unroll
        for (int g = 1; g < RPB; ++g) {
            s += sh[g * C + c];
            q += sh2[g * C + c];
        }
        atomicAdd(&gsum[c], s);
        atomicAdd(&gsq[c], q);
    }
}

// bnsilu with fused BN-finalize; output f16 k-permuted
template <int C>
__global__ void bnsilu_kernel(const float* __restrict__ X,
                              const float* __restrict__ gsum, const float* __restrict__ gsq,
                              const float* __restrict__ g, const float* __restrict__ be,
                              float invM, size_t total, __half* __restrict__ out) {
    __shared__ float ssc[C], sbi[C];
    if (threadIdx.x < C) {
        int c = threadIdx.x;
        float m = gsum[c] * invM;
        float v = gsq[c] * invM - m * m;
        float a = g[c] * rsqrtf(v + 1e-5f);
        ssc[c] = a;
        sbi[c] = be[c] - m * a;
    }
    __syncthreads();
    for (size_t i = (size_t)blockIdx.x * blockDim.x + threadIdx.x; i < total;
         i += (size_t)gridDim.x * blockDim.x) {
        int c = (int)(i & (size_t)(C - 1));
        float z = X[i] * ssc[c] + sbi[c];
        int s = c & 15, p = s >> 1, e = s & 1;
        int pos = ((p & 3) << 2) | ((p >> 2) << 1) | e;
        out[(i & ~(size_t)15) | (size_t)pos] = __float2half_rn(silu_(z));
    }
}

// f32 natural -> f16 k-permuted
__global__ void tohalf_kernel(const float* __restrict__ X, size_t total,
                              __half* __restrict__ out) {
    for (size_t i = (size_t)blockIdx.x * blockDim.x + threadIdx.x; i < total;
         i += (size_t)gridDim.x * blockDim.x) {
        int s = (int)(i & 15), p = s >> 1, e = s & 1;
        int pos = ((p & 3) << 2) | ((p >> 2) << 1) | e;
        out[(i & ~(size_t)15) | (size_t)pos] = __float2half_rn(X[i]);
    }
}

// W[k][c][n] -> fragment-major f16. block 0 zeroes stats; tail blocks do temb.
__global__ void transpose_w_kernel(const float* __restrict__ W, __half* __restrict__ Wt,
                                   int K, int CIN, float* stats_zero,
                                   const float* __restrict__ t, const float* __restrict__ Wtm,
                                   const float* __restrict__ bt, float* __restrict__ tp,
                                   int ntb) {
    if (ntb > 0 && (int)blockIdx.x >= (int)gridDim.x - ntb) {
        __shared__ float st[256];
        const int b = blockIdx.x - (gridDim.x - ntb);
        const int j = threadIdx.x;
        st[j] = silu_(t[b * 256 + j]);
        __syncthreads();
        float acc = bt[j];
        #pragma unroll 8
        for (int e = 0; e < 256; ++e) acc += st[e] * Wtm[e * 256 + j];
        tp[b * 256 + j] = acc;
        return;
    }
    if (stats_zero && blockIdx.x == 0) {
        for (int z = threadIdx.x; z < 384; z += blockDim.x) stats_zero[z] = 0.f;
    }
    const int nwb = gridDim.x - ntb;
    const int NCH = CIN >> 6;
    const int hpk = CIN * 128;          // halves per k
    const int total = K * hpk;
    for (int i = blockIdx.x * blockDim.x + threadIdx.x; i < total;
         i += nwb * blockDim.x) {
        int k = i / hpk;
        int rem = i - k * hpk;
        int blk = rem >> 7;             // NCH*64 blocks per k
        int off = rem & 127;
        int ch = blk >> 6;              // blk / 64
        int bj = blk & 63;
        int j = bj >> 2, g = bj & 3;
        int lr = off >> 4, lp = (off >> 2) & 3, slot = off & 3;
        int p = lp + ((slot >> 1) << 2);
        int e = slot & 1;
        int c = (ch << 6) | (g << 4) | (2 * p + e);
        int n = (j << 3) | lr;
        Wt[i] = __float2half_rn(W[(k * CIN + c) * 128 + n]);
    }
}

// ---------------- direct-LDG f16 m16n8k16 gathered sparse-conv GEMM ----------------
// 256-row x 128-col tile, 512 threads (16 warps = 8m x 2n of m32 x n64), f32 accum.
// No smem staging, no mainloop barriers: fragments loaded straight from global.
// MODE 0: + bias (+bias2); MODE 1: TE affine; MODE 2: + addend (f32)
template <int CIN, int MODE, bool IDENT>
__global__ void __launch_bounds__(CTHREADS, 1)
conv_mma(const __half* __restrict__ Af, const int* __restrict__ nbr, int K, int M,
         const __half* __restrict__ Wt,
         const float* __restrict__ bias, const float* __restrict__ bias2,
         float* __restrict__ out, const float* __restrict__ addend,
         const float* __restrict__ tp, const int* __restrict__ b_idx) {
    extern __shared__ float Cs[];

    const int tid = threadIdx.x;
    const int wid = tid >> 5, lane = tid & 31;
    const int wr = wid & 7, wc = wid >> 3;   // m0=32*wr, n0=64*wc
    const int lr = lane >> 2, lp = lane & 3;
    const int tile = blockIdx.x * 256;

    constexpr int NCH = CIN / 64;
    const int NC = K * NCH;

    float acc[2][8][4];
    #pragma unroll
    for (int t = 0; t < 2; ++t)
        #pragma unroll
        for (int j = 0; j < 8; ++j)
            #pragma unroll
            for (int i = 0; i < 4; ++i) acc[t][j][i] = 0.f;

    const int rbase = tile + 32 * wr + lr;

    for (int ci = 0; ci < NC; ++ci) {
        const int k = (NCH == 1) ? ci : (ci >> 1);
        const int ch = (NCH == 1) ? 0 : (ci & 1);

        // neighbor indices for this warp's 4 row-quads (L1-hot)
        int idxs[4];
        #pragma unroll
        for (int q = 0; q < 4; ++q) {
            int row = rbase + 8 * q;
            idxs[q] = (row < M) ? (IDENT ? row : __ldg(nbr + (size_t)k * M + row)) : -1;
        }
        const __half* aq[4];
        #pragma unroll
        for (int q = 0; q < 4; ++q)
            aq[q] = Af + (size_t)(idxs[q] < 0 ? 0 : idxs[q]) * CIN + ch * 64 + lp * 4;

        const __half* wb = Wt + ((size_t)(k * NCH + ch) * 64 + (size_t)wc * 32) * 128
                              + lane * 4;

        #pragma unroll
        for (int g = 0; g < 4; ++g) {
            // A fragments: predicated gather LDG.64 (zero for missing neighbors)
            uint2 al[4];
            #pragma unroll
            for (int q = 0; q < 4; ++q) {
                uint2 v = make_uint2(0u, 0u);
                if (idxs[q] >= 0) v = *(const uint2*)(aq[q] + g * 16);
                al[q] = v;
            }
            uint32_t a[2][4];
            #pragma unroll
            for (int t = 0; t < 2; ++t) {
                a[t][0] = al[2 * t].x;     // row lr,    k-lo
                a[t][1] = al[2 * t + 1].x; // row lr+8,  k-lo
                a[t][2] = al[2 * t].y;     // row lr,    k-hi
                a[t][3] = al[2 * t + 1].y; // row lr+8,  k-hi
            }
            // B fragments: fragment-major coalesced LDG.64 (L1-resident)
            #pragma unroll
            for (int j = 0; j < 8; ++j) {
                uint2 b = *(const uint2*)(wb + (size_t)(j * 4 + g) * 128);
                mma16(acc[0][j], a[0], b.x, b.y);
                mma16(acc[1][j], a[1], b.x, b.y);
            }
        }
    }

    // ---- stage C through smem for coalesced stores ----
    __syncthreads();
    #pragma unroll
    for (int t = 0; t < 2; ++t)
        #pragma unroll
        for (int j = 0; j < 8; ++j) {
            int r0 = 32 * wr + 16 * t + lr;
            int cc0 = 64 * wc + 8 * j + 2 * lp;
            *(float2*)&Cs[r0 * SC + cc0] = make_float2(acc[t][j][0], acc[t][j][1]);
            *(float2*)&Cs[(r0 + 8) * SC + cc0] = make_float2(acc[t][j][2], acc[t][j][3]);
        }
    __syncthreads();

    // ---- epilogue: thread -> (row, half) ----
    const int r = tid >> 1;
    const int hf = tid & 1;
    const int row = tile + r;
    if (row < M) {
        const float* tpr = nullptr;
        if (MODE == 1) tpr = tp + b_idx[row] * 256;
        #pragma unroll 4
        for (int q = 0; q < 16; ++q) {
            const int p0 = hf * 64 + q * 4;
            float v[4];
            #pragma unroll
            for (int i = 0; i < 4; ++i) v[i] = Cs[r * SC + p0 + i];
            float4 ad;
            if (MODE == 2) ad = *(const float4*)(addend + (size_t)row * NFW + p0);
            #pragma unroll
            for (int i = 0; i < 4; ++i) {
                if (MODE == 0) {
                    if (bias) v[i] += bias[p0 + i];
                    if (bias2) v[i] += bias2[p0 + i];
                } else if (MODE == 1) {
                    v[i] = (1.f + tpr[p0 + i]) * (v[i] + bias[p0 + i]) + tpr[128 + p0 + i];
                } else {
                    v[i] += (&ad.x)[i];
                }
            }
            *(float4*)(out + (size_t)row * NFW + p0) = make_float4(v[0], v[1], v[2], v[3]);
        }
    }
}

// ---------------- launch ----------------
extern "C" void kernel_launch(void* const* d_in, const int* in_sizes, int n_in,
                              void* d_out, int out_size) {
    const float* x        = (const float*)d_in[0];
    const float* t        = (const float*)d_in[1];
    const int*   b_idx    = (const int*)d_in[2];
    const int*   nbr      = (const int*)d_in[3];
    const int*   nbr_down = (const int*)d_in[4];
    const float* g1       = (const float*)d_in[5];
    const float* be1      = (const float*)d_in[6];
    const float* W1       = (const float*)d_in[7];
    const float* b1       = (const float*)d_in[8];
    const float* Wtm      = (const float*)d_in[9];
    const float* bt       = (const float*)d_in[10];
    const float* g2       = (const float*)d_in[11];
    const float* be2      = (const float*)d_in[12];
    const float* W2       = (const float*)d_in[13];
    const float* b2       = (const float*)d_in[14];
    const float* Wid      = (const float*)d_in[15];
    const float* bid      = (const float*)d_in[16];
    const float* Wd       = (const float*)d_in[17];
    float* out = (float*)d_out;

    float *ph, *ph2, *pstats, *ptp;
    __half *pa, *pwt;
    cudaGetSymbolAddress((void**)&pa, g_a);
    cudaGetSymbolAddress((void**)&ph, g_h);
    cudaGetSymbolAddress((void**)&ph2, g_h2);
    cudaGetSymbolAddress((void**)&pstats, g_stats);
    cudaGetSymbolAddress((void**)&ptp, g_tp);
    cudaGetSymbolAddress((void**)&pwt, g_wt);

    cudaFuncSetAttribute(conv_mma<64, 1, false>,
                         cudaFuncAttributeMaxDynamicSharedMemorySize, SMEM_BYTES);
    cudaFuncSetAttribute(conv_mma<64, 0, true>,
                         cudaFuncAttributeMaxDynamicSharedMemorySize, SMEM_BYTES);
    cudaFuncSetAttribute(conv_mma<128, 2, false>,
                         cudaFuncAttributeMaxDynamicSharedMemorySize, SMEM_BYTES);
    cudaFuncSetAttribute(conv_mma<128, 0, false>,
                         cudaFuncAttributeMaxDynamicSharedMemorySize, SMEM_BYTES);

    const int N = in_sizes[0] / 64;             // 200000
    const int K = in_sizes[3] / N;              // 27
    const int KD = in_sizes[17] / (128 * 128);  // 8
    const int ND = in_sizes[4] / KD;            // 25000
    const float invN = 1.f / (float)N;
    const int GN = (N + 255) / 256;
    const int GD = (ND + 255) / 256;
    __half* pxh = pa + (size_t)N * 64;          // f16-permuted x (second half of g_a)

    // Launch order: conv1 at launch #4 (the ncu-captured slot).
    // 1: W1 transpose (fragment-major) + zero stats + temb (16 tail blocks)
    transpose_w_kernel<<<232, 256>>>(W1, pwt + WT1_OFF, K, 64, pstats, t, Wtm, bt, ptp, 16);
    // 2: BN1 stats
    stats_kernel<64><<<512, 256>>>(x, N, pstats + 0, pstats + 64);
    // 3: bnsilu1 (fused finalize) -> g_a[0:N*64]
    bnsilu_kernel<64><<<2048, 256>>>(x, pstats + 0, pstats + 64, g1, be1, invN,
                                     (size_t)N * 64, pa);
    // 4: conv1 (64->128) + b1 + TE affine -> g_h   << ncu capture slot
    conv_mma<64, 1, false><<<GN, CTHREADS, SMEM_BYTES>>>(
        pa, nbr, K, N, pwt + WT1_OFF, b1, nullptr, ph, nullptr, ptp, b_idx);

    // 5: x -> f16 permuted (for idconv)
    tohalf_kernel<<<2048, 256>>>(x, (size_t)N * 64, pxh);
    // 6: W2 transpose
    transpose_w_kernel<<<432, 256>>>(W2, pwt + WT2_OFF, K, 128, nullptr,
                                     nullptr, nullptr, nullptr, nullptr, 0);
    // 7: BN2 stats
    stats_kernel<128><<<512, 256>>>(ph, N, pstats + 128, pstats + 256);
    // 8: Wid transpose
    transpose_w_kernel<<<32, 256>>>(Wid, pwt + WTID_OFF, 1, 64, nullptr,
                                    nullptr, nullptr, nullptr, nullptr, 0);
    // 9: idconv: h2 = x @ Wid + bid + b2  (uses xhalf; before bnsilu2 clobbers it)
    conv_mma<64, 0, true><<<GN, CTHREADS, SMEM_BYTES>>>(
        pxh, nullptr, 1, N, pwt + WTID_OFF, bid, b2, ph2, nullptr, nullptr, nullptr);
    // 10: bnsilu2 (fused finalize) -> g_a (full N*128)
    bnsilu_kernel<128><<<2048, 256>>>(ph, pstats + 128, pstats + 256, g2, be2, invN,
                                      (size_t)N * 128, pa);
    // 11: conv2 (128->128) + h2 addend -> g_h2
    conv_mma<128, 2, false><<<GN, CTHREADS, SMEM_BYTES>>>(
        pa, nbr, K, N, pwt + WT2_OFF, nullptr, nullptr, ph2, ph2, nullptr, nullptr);
    // 12: Wd transpose
    transpose_w_kernel<<<128, 256>>>(Wd, pwt + WTD_OFF, KD, 128, nullptr,
                                     nullptr, nullptr, nullptr, nullptr, 0);
    // 13: h2 -> f16 permuted
    tohalf_kernel<<<2048, 256>>>(ph2, (size_t)N * 128, pa);
    // 14: strided down conv (8 taps) -> out [ND, 128]
    conv_mma<128, 0, false><<<GD, CTHREADS, SMEM_BYTES>>>(
        pa, nbr_down, KD, ND, pwt + WTD_OFF, nullptr, nullptr, out,
        nullptr, nullptr, nullptr);
}

// round 13
// speedup vs baseline: 3.6733x; 1.0243x over previous
#include <cuda_runtime.h>
#include <cuda_fp16.h>
#include <cstdint>

#define N_VOX 200000
#define NFW 128
#define SC 136                       // C staging row stride (floats)
#define SMEM_BYTES (256 * SC * 4)    // 139264 B (epilogue staging only)
#define CTHREADS 512                 // 16 warps: 8m x 2n of m32 x n64

// ---------------- scratch (static device globals; no allocation) ----------------
__device__ __half g_a[(size_t)N_VOX * 128];  // f16 k-permuted activations
__device__ float g_h[(size_t)N_VOX * 128];   // conv1 output h (f32 natural)
__device__ float g_h2[(size_t)N_VOX * 128];  // idconv + conv2 output (f32 natural)
__device__ float g_stats[384];
__device__ float g_tp[16 * 256];
__device__ __half g_wt[802816];              // fragment-major f16 weights

#define WT1_OFF 0
#define WT2_OFF (27 * 128 * 64)
#define WTD_OFF (WT2_OFF + 27 * 128 * 128)
#define WTID_OFF (WTD_OFF + 8 * 128 * 128)

// A permutation within each 64-half chunk: for group-pair gp (groups 2gp,2gp+1),
// lane lp owns one 16B run at pos = gp*32 + lp*8 containing
// [g_even: {2lp,2lp+1,2lp+8,2lp+9}, g_odd: same] -> one LDG.128 = 2 groups' a-frags.
// c = ch*64 + g*16 + 2lp + 8hi + e  ->  pos6 = ((g>>1)<<5)|(lp<<3)|((g&1)<<2)|(hi<<1)|e
//
// W fragment-major superblocks of 256 halves: per (k,ch), superblock sb = jg*2+gp
// (jg in 0..15 over n=8*jg+lr); within: off = lane*8 + gg*4 + slot.

// ---------------- helpers ----------------
__device__ __forceinline__ float silu_(float z) {
    return z * (1.f / (1.f + __expf(-z)));
}
__device__ __forceinline__ void mma16(float* c, const uint32_t* a, uint32_t b0, uint32_t b1) {
    asm volatile(
        "mma.sync.aligned.m16n8k16.row.col.f32.f16.f16.f32 "
        "{%0,%1,%2,%3}, {%4,%5,%6,%7}, {%8,%9}, {%0,%1,%2,%3};"
        : "+f"(c[0]), "+f"(c[1]), "+f"(c[2]), "+f"(c[3])
        : "r"(a[0]), "r"(a[1]), "r"(a[2]), "r"(a[3]), "r"(b0), "r"(b1));
}
__device__ __forceinline__ int permpos64(int c6) {
    int g = c6 >> 4, h = c6 & 15;
    int lp = (h >> 1) & 3, hi = h >> 3, e = h & 1;
    return ((g >> 1) << 5) | (lp << 3) | ((g & 1) << 2) | (hi << 1) | e;
}

// ---------------- small kernels ----------------
template <int C>
__global__ void stats_kernel(const float* __restrict__ X, int M,
                             float* __restrict__ gsum, float* __restrict__ gsq) {
    constexpr int RPB = 256 / C;
    const int c = threadIdx.x & (C - 1);
    const int rg = threadIdx.x / C;
    float s = 0.f, q = 0.f;
    for (int r = blockIdx.x * RPB + rg; r < M; r += gridDim.x * RPB) {
        float v = X[(size_t)r * C + c];
        s += v;
        q += v * v;
    }
    __shared__ float sh[256];
    __shared__ float sh2[256];
    sh[threadIdx.x] = s;
    sh2[threadIdx.x] = q;
    __syncthreads();
    if (threadIdx.x < C) {
        #pragma unroll
        for (int g = 1; g < RPB; ++g) {
            s += sh[g * C + c];
            q += sh2[g * C + c];
        }
        atomicAdd(&gsum[c], s);
        atomicAdd(&gsq[c], q);
    }
}

// bnsilu with fused BN-finalize; output f16 k-permuted (64-half chunks)
template <int C>
__global__ void bnsilu_kernel(const float* __restrict__ X,
                              const float* __restrict__ gsum, const float* __restrict__ gsq,
                              const float* __restrict__ g, const float* __restrict__ be,
                              float invM, size_t total, __half* __restrict__ out) {
    __shared__ float ssc[C], sbi[C];
    if (threadIdx.x < C) {
        int c = threadIdx.x;
        float m = gsum[c] * invM;
        float v = gsq[c] * invM - m * m;
        float a = g[c] * rsqrtf(v + 1e-5f);
        ssc[c] = a;
        sbi[c] = be[c] - m * a;
    }
    __syncthreads();
    for (size_t i = (size_t)blockIdx.x * blockDim.x + threadIdx.x; i < total;
         i += (size_t)gridDim.x * blockDim.x) {
        int c = (int)(i & (size_t)(C - 1));
        float z = X[i] * ssc[c] + sbi[c];
        int pos = permpos64((int)(i & 63));
        out[(i & ~(size_t)63) | (size_t)pos] = __float2half_rn(silu_(z));
    }
}

// f32 natural -> f16 k-permuted (64-half chunks)
__global__ void tohalf_kernel(const float* __restrict__ X, size_t total,
                              __half* __restrict__ out) {
    for (size_t i = (size_t)blockIdx.x * blockDim.x + threadIdx.x; i < total;
         i += (size_t)gridDim.x * blockDim.x) {
        int pos = permpos64((int)(i & 63));
        out[(i & ~(size_t)63) | (size_t)pos] = __float2half_rn(X[i]);
    }
}

// W[k][c][n] -> fragment-major superblocks. block 0 zeroes stats; tail blocks temb.
__global__ void transpose_w_kernel(const float* __restrict__ W, __half* __restrict__ Wt,
                                   int K, int CIN, float* stats_zero,
                                   const float* __restrict__ t, const float* __restrict__ Wtm,
                                   const float* __restrict__ bt, float* __restrict__ tp,
                                   int ntb) {
    if (ntb > 0 && (int)blockIdx.x >= (int)gridDim.x - ntb) {
        __shared__ float st[256];
        const int b = blockIdx.x - (gridDim.x - ntb);
        const int j = threadIdx.x;
        st[j] = silu_(t[b * 256 + j]);
        __syncthreads();
        float acc = bt[j];
        #pragma unroll 8
        for (int e = 0; e < 256; ++e) acc += st[e] * Wtm[e * 256 + j];
        tp[b * 256 + j] = acc;
        return;
    }
    if (stats_zero && blockIdx.x == 0) {
        for (int z = threadIdx.x; z < 384; z += blockDim.x) stats_zero[z] = 0.f;
    }
    const int nwb = gridDim.x - ntb;
    const int hpk = CIN * 128;          // halves per k
    const int total = K * hpk;
    for (int i = blockIdx.x * blockDim.x + threadIdx.x; i < total;
         i += nwb * blockDim.x) {
        int k = i / hpk;
        int rem = i - k * hpk;
        int sblk = rem >> 8;            // 256-half superblocks
        int off = rem & 255;
        int ch = sblk >> 5;             // superblock / 32
        int sb = sblk & 31;
        int jg = sb >> 1, gp = sb & 1;
        int lane = off >> 3, gg = (off >> 2) & 1, slot = off & 3;
        int lr = lane >> 2, lp = lane & 3;
        int g = gp * 2 + gg;
        int hi = slot >> 1, e = slot & 1;
        int c = (ch << 6) | (g << 4) | (2 * lp + 8 * hi + e);
        int n = (jg << 3) | lr;
        Wt[i] = __float2half_rn(W[(k * CIN + c) * 128 + n]);
    }
}

// ---------------- direct-LDG.128 f16 m16n8k16 gathered sparse-conv GEMM ----------------
// 256-row x 128-col tile, 512 threads (16 warps = 8m x 2n of m32 x n64), f32 accum.
// No smem staging, no mainloop barriers; all fragment loads are LDG.128.
// MODE 0: + bias (+bias2); MODE 1: TE affine; MODE 2: + addend (f32)
template <int CIN, int MODE, bool IDENT>
__global__ void __launch_bounds__(CTHREADS, 1)
conv_mma(const __half* __restrict__ Af, const int* __restrict__ nbr, int K, int M,
         const __half* __restrict__ Wt,
         const float* __restrict__ bias, const float* __restrict__ bias2,
         float* __restrict__ out, const float* __restrict__ addend,
         const float* __restrict__ tp, const int* __restrict__ b_idx) {
    extern __shared__ float Cs[];

    const int tid = threadIdx.x;
    const int wid = tid >> 5, lane = tid & 31;
    const int wr = wid & 7, wc = wid >> 3;   // m0=32*wr, n0=64*wc
    const int lr = lane >> 2, lp = lane & 3;
    const int tile = blockIdx.x * 256;

    constexpr int NCH = CIN / 64;
    const int NC = K * NCH;

    float acc[2][8][4];
    #pragma unroll
    for (int t = 0; t < 2; ++t)
        #pragma unroll
        for (int j = 0; j < 8; ++j)
            #pragma unroll
            for (int i = 0; i < 4; ++i) acc[t][j][i] = 0.f;

    const int rbase = tile + 32 * wr + lr;

    for (int ci = 0; ci < NC; ++ci) {
        const int k = (NCH == 1) ? ci : (ci >> 1);
        const int ch = (NCH == 1) ? 0 : (ci & 1);

        int idxs[4];
        #pragma unroll
        for (int q = 0; q < 4; ++q) {
            int row = rbase + 8 * q;
            idxs[q] = (row < M) ? (IDENT ? row : __ldg(nbr + (size_t)k * M + row)) : -1;
        }
        const __half* aq[4];
        #pragma unroll
        for (int q = 0; q < 4; ++q)
            aq[q] = Af + (size_t)(idxs[q] < 0 ? 0 : idxs[q]) * CIN + ch * 64 + lp * 8;

        const __half* wb = Wt + ((size_t)(k * NCH + ch) * 32 + (size_t)wc * 16) * 256
                              + lane * 8;

        #pragma unroll
        for (int gp = 0; gp < 2; ++gp) {
            // A fragments: one LDG.128 per row-quad covers BOTH groups of the pair
            uint4 al[4];
            #pragma unroll
            for (int q = 0; q < 4; ++q) {
                uint4 v = make_uint4(0u, 0u, 0u, 0u);
                if (idxs[q] >= 0) v = *(const uint4*)(aq[q] + gp * 32);
                al[q] = v;
            }
            uint32_t a0[2][4], a1[2][4];
            #pragma unroll
            for (int t = 0; t < 2; ++t) {
                a0[t][0] = al[2 * t].x;     a0[t][1] = al[2 * t + 1].x;
                a0[t][2] = al[2 * t].y;     a0[t][3] = al[2 * t + 1].y;
                a1[t][0] = al[2 * t].z;     a1[t][1] = al[2 * t + 1].z;
                a1[t][2] = al[2 * t].w;     a1[t][3] = al[2 * t + 1].w;
            }
            // B fragments: one LDG.128 per j covers both groups of the pair
            #pragma unroll
            for (int j = 0; j < 8; ++j) {
                uint4 b = *(const uint4*)(wb + (size_t)(j * 2 + gp) * 256);
                mma16(acc[0][j], a0[0], b.x, b.y);
                mma16(acc[1][j], a0[1], b.x, b.y);
                mma16(acc[0][j], a1[0], b.z, b.w);
                mma16(acc[1][j], a1[1], b.z, b.w);
            }
        }
    }

    // ---- stage C through smem for coalesced stores ----
    __syncthreads();
    #pragma unroll
    for (int t = 0; t < 2; ++t)
        #pragma unroll
        for (int j = 0; j < 8; ++j) {
            int r0 = 32 * wr + 16 * t + lr;
            int cc0 = 64 * wc + 8 * j + 2 * lp;
            *(float2*)&Cs[r0 * SC + cc0] = make_float2(acc[t][j][0], acc[t][j][1]);
            *(float2*)&Cs[(r0 + 8) * SC + cc0] = make_float2(acc[t][j][2], acc[t][j][3]);
        }
    __syncthreads();

    // ---- epilogue: thread -> (row, half) ----
    const int r = tid >> 1;
    const int hf = tid & 1;
    const int row = tile + r;
    if (row < M) {
        const float* tpr = nullptr;
        if (MODE == 1) tpr = tp + b_idx[row] * 256;
        #pragma unroll 4
        for (int q = 0; q < 16; ++q) {
            const int p0 = hf * 64 + q * 4;
            float v[4];
            #pragma unroll
            for (int i = 0; i < 4; ++i) v[i] = Cs[r * SC + p0 + i];
            float4 ad;
            if (MODE == 2) ad = *(const float4*)(addend + (size_t)row * NFW + p0);
            #pragma unroll
            for (int i = 0; i < 4; ++i) {
                if (MODE == 0) {
                    if (bias) v[i] += bias[p0 + i];
                    if (bias2) v[i] += bias2[p0 + i];
                } else if (MODE == 1) {
                    v[i] = (1.f + tpr[p0 + i]) * (v[i] + bias[p0 + i]) + tpr[128 + p0 + i];
                } else {
                    v[i] += (&ad.x)[i];
                }
            }
            *(float4*)(out + (size_t)row * NFW + p0) = make_float4(v[0], v[1], v[2], v[3]);
        }
    }
}

// ---------------- launch ----------------
extern "C" void kernel_launch(void* const* d_in, const int* in_sizes, int n_in,
                              void* d_out, int out_size) {
    const float* x        = (const float*)d_in[0];
    const float* t        = (const float*)d_in[1];
    const int*   b_idx    = (const int*)d_in[2];
    const int*   nbr      = (const int*)d_in[3];
    const int*   nbr_down = (const int*)d_in[4];
    const float* g1       = (const float*)d_in[5];
    const float* be1      = (const float*)d_in[6];
    const float* W1       = (const float*)d_in[7];
    const float* b1       = (const float*)d_in[8];
    const float* Wtm      = (const float*)d_in[9];
    const float* bt       = (const float*)d_in[10];
    const float* g2       = (const float*)d_in[11];
    const float* be2      = (const float*)d_in[12];
    const float* W2       = (const float*)d_in[13];
    const float* b2       = (const float*)d_in[14];
    const float* Wid      = (const float*)d_in[15];
    const float* bid      = (const float*)d_in[16];
    const float* Wd       = (const float*)d_in[17];
    float* out = (float*)d_out;

    float *ph, *ph2, *pstats, *ptp;
    __half *pa, *pwt;
    cudaGetSymbolAddress((void**)&pa, g_a);
    cudaGetSymbolAddress((void**)&ph, g_h);
    cudaGetSymbolAddress((void**)&ph2, g_h2);
    cudaGetSymbolAddress((void**)&pstats, g_stats);
    cudaGetSymbolAddress((void**)&ptp, g_tp);
    cudaGetSymbolAddress((void**)&pwt, g_wt);

    cudaFuncSetAttribute(conv_mma<64, 1, false>,
                         cudaFuncAttributeMaxDynamicSharedMemorySize, SMEM_BYTES);
    cudaFuncSetAttribute(conv_mma<64, 0, true>,
                         cudaFuncAttributeMaxDynamicSharedMemorySize, SMEM_BYTES);
    cudaFuncSetAttribute(conv_mma<128, 2, false>,
                         cudaFuncAttributeMaxDynamicSharedMemorySize, SMEM_BYTES);
    cudaFuncSetAttribute(conv_mma<128, 0, false>,
                         cudaFuncAttributeMaxDynamicSharedMemorySize, SMEM_BYTES);

    const int N = in_sizes[0] / 64;             // 200000
    const int K = in_sizes[3] / N;              // 27
    const int KD = in_sizes[17] / (128 * 128);  // 8
    const int ND = in_sizes[4] / KD;            // 25000
    const float invN = 1.f / (float)N;
    const int GN = (N + 255) / 256;
    const int GD = (ND + 255) / 256;
    __half* pxh = pa + (size_t)N * 64;          // f16-permuted x (second half of g_a)

    // Launch order: conv1 at launch #4 (the ncu-captured slot).
    // 1: W1 transpose (fragment-major) + zero stats + temb (16 tail blocks)
    transpose_w_kernel<<<232, 256>>>(W1, pwt + WT1_OFF, K, 64, pstats, t, Wtm, bt, ptp, 16);
    // 2: BN1 stats
    stats_kernel<64><<<512, 256>>>(x, N, pstats + 0, pstats + 64);
    // 3: bnsilu1 (fused finalize) -> g_a[0:N*64]
    bnsilu_kernel<64><<<2048, 256>>>(x, pstats + 0, pstats + 64, g1, be1, invN,
                                     (size_t)N * 64, pa);
    // 4: conv1 (64->128) + b1 + TE affine -> g_h   << ncu capture slot
    conv_mma<64, 1, false><<<GN, CTHREADS, SMEM_BYTES>>>(
        pa, nbr, K, N, pwt + WT1_OFF, b1, nullptr, ph, nullptr, ptp, b_idx);

    // 5: x -> f16 permuted (for idconv)
    tohalf_kernel<<<2048, 256>>>(x, (size_t)N * 64, pxh);
    // 6: W2 transpose
    transpose_w_kernel<<<432, 256>>>(W2, pwt + WT2_OFF, K, 128, nullptr,
                                     nullptr, nullptr, nullptr, nullptr, 0);
    // 7: BN2 stats
    stats_kernel<128><<<512, 256>>>(ph, N, pstats + 128, pstats + 256);
    // 8: Wid transpose
    transpose_w_kernel<<<32, 256>>>(Wid, pwt + WTID_OFF, 1, 64, nullptr,
                                    nullptr, nullptr, nullptr, nullptr, 0);
    // 9: idconv: h2 = x @ Wid + bid + b2
    conv_mma<64, 0, true><<<GN, CTHREADS, SMEM_BYTES>>>(
        pxh, nullptr, 1, N, pwt + WTID_OFF, bid, b2, ph2, nullptr, nullptr, nullptr);
    // 10: bnsilu2 (fused finalize) -> g_a (full N*128)
    bnsilu_kernel<128><<<2048, 256>>>(ph, pstats + 128, pstats + 256, g2, be2, invN,
                                      (size_t)N * 128, pa);
    // 11: conv2 (128->128) + h2 addend -> g_h2
    conv_mma<128, 2, false><<<GN, CTHREADS, SMEM_BYTES>>>(
        pa, nbr, K, N, pwt + WT2_OFF, nullptr, nullptr, ph2, ph2, nullptr, nullptr);
    // 12: Wd transpose
    transpose_w_kernel<<<128, 256>>>(Wd, pwt + WTD_OFF, KD, 128, nullptr,
                                     nullptr, nullptr, nullptr, nullptr, 0);
    // 13: h2 -> f16 permuted
    tohalf_kernel<<<2048, 256>>>(ph2, (size_t)N * 128, pa);
    // 14: strided down conv (8 taps) -> out [ND, 128]
    conv_mma<128, 0, false><<<GD, CTHREADS, SMEM_BYTES>>>(
        pa, nbr_down, KD, ND, pwt + WTD_OFF, nullptr, nullptr, out,
        nullptr, nullptr, nullptr);
}